// round 14
// baseline (speedup 1.0000x reference)
#include <cuda_runtime.h>
#include <cuda_bf16.h>
#include <cstddef>

#define Bb 4
#define Nn 4096
#define DIMV 512
#define Hh 8
#define Dd 64
#define Mm 256
#define BHc 32
#define QSCALE 0.125f

// ---------------- scratch ----------------
__device__ __nv_bfloat16 g_q   [BHc*Nn*Dd];
__device__ __nv_bfloat16 g_k   [BHc*Nn*Dd];
__device__ __nv_bfloat16 g_v   [BHc*Nn*Dd];
__device__ __nv_bfloat16 g_ql  [BHc*Mm*Dd];
__device__ __nv_bfloat16 g_kl  [BHc*Mm*Dd];
__device__ float         g_a2f [BHc*Mm*Mm];
__device__ __nv_bfloat16 g_a2h [BHc*Mm*Mm];   // A2; per-matrix reused as y ping buffer
__device__ __nv_bfloat16 g_z   [BHc*Mm*Mm];
__device__ __nv_bfloat16 g_zn  [BHc*Mm*Mm];
__device__ __nv_bfloat16 g_az  [BHc*Mm*Mm];   // y
__device__ __nv_bfloat16 g_w1  [BHc*Mm*Mm];   // y^2
__device__ __nv_bfloat16 g_w2  [BHc*Mm*Mm];   // r
__device__ __nv_bfloat16 g_a3v [BHc*Mm*Dd];
__device__ __nv_bfloat16 g_wm  [BHc*Mm*Dd];
__device__ __nv_bfloat16 g_outh[BHc*Nn*Dd];
__device__ __nv_bfloat16 g_cvh [BHc*Nn*Dd];
__device__ float g_mu[Bb*Nn];
__device__ float g_rs[Bb*Nn];
__device__ float g_ms2;
__device__ float g_fO[BHc*4*4*4096];
__device__ float g_fm[BHc*4*4*64];
__device__ float g_fl[BHc*4*4*64];

__device__ __forceinline__ unsigned packbf(float a, float b) {
    __nv_bfloat162 t = __floats2bfloat162_rn(a, b);
    return *reinterpret_cast<unsigned*>(&t);
}
__device__ __forceinline__ float2 unpackbf(unsigned u) {
    __nv_bfloat162 t = *reinterpret_cast<__nv_bfloat162*>(&u);
    return make_float2(__bfloat162float(t.x), __bfloat162float(t.y));
}
__device__ __forceinline__ void mma16(float* c, const unsigned* a, const unsigned* b) {
    asm volatile("mma.sync.aligned.m16n8k16.row.col.f32.bf16.bf16.f32 "
                 "{%0,%1,%2,%3},{%4,%5,%6,%7},{%8,%9},{%0,%1,%2,%3};"
                 : "+f"(c[0]), "+f"(c[1]), "+f"(c[2]), "+f"(c[3])
                 : "r"(a[0]), "r"(a[1]), "r"(a[2]), "r"(a[3]), "r"(b[0]), "r"(b[1]));
}

// ---------------- small kernels ----------------
__global__ void k_lnstats(const float* __restrict__ x) {
    int r = blockIdx.x, t = threadIdx.x;
    if (r == 0 && t == 0) g_ms2 = 0.f;
    const float* xp = x + (size_t)r * DIMV;
    float v0 = xp[t], v1 = xp[t + 256];
    __shared__ float red[256];
    red[t] = v0 + v1; __syncthreads();
    for (int s = 128; s; s >>= 1) { if (t < s) red[t] += red[t + s]; __syncthreads(); }
    float mean = red[0] * (1.f / 512.f);
    __syncthreads();
    float d0 = v0 - mean, d1 = v1 - mean;
    red[t] = d0 * d0 + d1 * d1; __syncthreads();
    for (int s = 128; s; s >>= 1) { if (t < s) red[t] += red[t + s]; __syncthreads(); }
    if (t == 0) { g_mu[r] = mean; g_rs[r] = rsqrtf(red[0] * (1.f / 512.f) + 1e-5f); }
}

__global__ void k_land() {
    int idx = blockIdx.x * 256 + threadIdx.x;
    int sel = idx >= (BHc * Mm * 32);
    int e = idx & (BHc * Mm * 32 - 1);
    int bh = e >> 13, j = (e >> 5) & 255, dp = e & 31;
    const __nv_bfloat16* src = sel ? g_k : g_q;
    const __nv_bfloat16* p = src + ((size_t)bh * 4096 + j * 16) * 64 + dp * 2;
    float s0 = 0.f, s1 = 0.f;
#pragma unroll
    for (int t = 0; t < 16; t++) {
        float2 f = unpackbf(*(const unsigned*)(p + t * 64));
        s0 += f.x; s1 += f.y;
    }
    __nv_bfloat16* dst = sel ? g_kl : g_ql;
    *(unsigned*)(dst + (size_t)bh * 16384 + j * 64 + dp * 2) =
        packbf(s0 * (1.f / 16.f), s1 * (1.f / 16.f));
}

__global__ void k_sums(const float* __restrict__ a) {
    int mat = blockIdx.x, t = threadIdx.x;
    const float* A = a + (size_t)mat * 65536;
    float cs = 0.f;
    for (int i = 0; i < 256; i++) cs += A[i * 256 + t];
    __shared__ float red[256];
    red[t] = cs; __syncthreads();
    for (int s = 128; s; s >>= 1) { if (t < s) red[t] = fmaxf(red[t], red[t + s]); __syncthreads(); }
    if (!t) atomicMax((int*)&g_ms2, __float_as_int(red[0]));
}

__global__ void k_z0() {
    int p = blockIdx.x * 256 + threadIdx.x;
    float inv = 1.f / g_ms2;
    int mat = p >> 15, rem = p & 32767;
    int r = rem >> 7, cp = (rem & 127) * 2;
    const float* A = g_a2f + ((size_t)mat << 16);
    float t0 = A[(size_t)cp * 256 + r], t1 = A[(size_t)(cp + 1) * 256 + r];
    *(unsigned*)(g_z + ((size_t)mat << 16) + (size_t)r * 256 + cp) = packbf(t0 * inv, t1 * inv);
}

__global__ void k_conv2(const float* __restrict__ w) {
    int nt = blockIdx.x, bh = blockIdx.y;
    __shared__ float vs[160][64];
    const __nv_bfloat16* vp = g_v + ((size_t)bh << 18);
    int n0 = nt * 128;
    for (int i = threadIdx.x; i < 160 * 8; i += 256) {
        int r = i >> 3, g = i & 7;
        int n = n0 - 16 + r;
        if (n >= 0 && n < 4096) {
            uint4 u = *(const uint4*)(vp + (size_t)n * 64 + g * 8);
            float2 f0 = unpackbf(u.x), f1 = unpackbf(u.y), f2 = unpackbf(u.z), f3 = unpackbf(u.w);
            vs[r][g * 8 + 0] = f0.x; vs[r][g * 8 + 1] = f0.y;
            vs[r][g * 8 + 2] = f1.x; vs[r][g * 8 + 3] = f1.y;
            vs[r][g * 8 + 4] = f2.x; vs[r][g * 8 + 5] = f2.y;
            vs[r][g * 8 + 6] = f3.x; vs[r][g * 8 + 7] = f3.y;
        } else {
#pragma unroll
            for (int q = 0; q < 8; q++) vs[r][g * 8 + q] = 0.f;
        }
    }
    __syncthreads();
    int h = bh & 7;
    float wr[33];
#pragma unroll
    for (int t = 0; t < 33; t++) wr[t] = w[h * 33 + t];
    int dp = threadIdx.x & 31, nl = threadIdx.x >> 5;
    for (int p = 0; p < 16; p++) {
        int n = nl + p * 8;
        float a0 = 0.f, a1 = 0.f;
#pragma unroll
        for (int t = 0; t < 33; t++) {
            a0 += wr[t] * vs[n + t][dp * 2];
            a1 += wr[t] * vs[n + t][dp * 2 + 1];
        }
        *(unsigned*)(g_cvh + ((size_t)bh * 4096 + n0 + n) * 64 + dp * 2) = packbf(a0, a1);
    }
}

// ---------------- fused scores+softmax, 64 rows/block ----------------
__global__ __launch_bounds__(128) void k_score2() {
    int bx = blockIdx.x, bh = blockIdx.y;
    extern __shared__ unsigned sm[];
    unsigned* Qs  = sm;
    unsigned* KLs = sm + 2304;
    const __nv_bfloat16* qlp = g_ql + (size_t)bh * 16384 + (size_t)bx * 64 * 64;
    const __nv_bfloat16* klp = g_kl + (size_t)bh * 16384;
    int tid = threadIdx.x, lane = tid & 31, w = tid >> 5;
    int r0 = lane >> 2, kq = lane & 3;
    int wrow = w * 16;

    {
        int r = tid >> 1, h = tid & 1;
        const __nv_bfloat16* ap = qlp + r * 64 + h * 32;
        unsigned* dst = &Qs[r * 36 + h * 16];
#pragma unroll
        for (int i = 0; i < 4; i++) *(uint4*)&dst[i * 4] = ((const uint4*)ap)[i];
    }
#pragma unroll
    for (int rr = 0; rr < 2; rr++) {
        int r = tid + rr * 128;
        const __nv_bfloat16* ap = klp + r * 64;
        unsigned* dst = &KLs[r * 36];
#pragma unroll
        for (int i = 0; i < 8; i++) *(uint4*)&dst[i * 4] = ((const uint4*)ap)[i];
    }
    __syncthreads();

    float sc[32][4];
#pragma unroll
    for (int j = 0; j < 32; j++)
#pragma unroll
        for (int q = 0; q < 4; q++) sc[j][q] = 0.f;
#pragma unroll
    for (int ks = 0; ks < 4; ks++) {
        int kb = ks * 8;
        unsigned a[4];
        a[0] = Qs[(wrow + r0) * 36 + kb + kq];
        a[1] = Qs[(wrow + r0 + 8) * 36 + kb + kq];
        a[2] = Qs[(wrow + r0) * 36 + kb + kq + 4];
        a[3] = Qs[(wrow + r0 + 8) * 36 + kb + kq + 4];
#pragma unroll
        for (int j = 0; j < 32; j++) {
            unsigned b[2] = { KLs[(j * 8 + r0) * 36 + kb + kq],
                              KLs[(j * 8 + r0) * 36 + kb + kq + 4] };
            mma16(sc[j], a, b);
        }
    }
    float m0 = -1e30f, m1 = -1e30f;
#pragma unroll
    for (int j = 0; j < 32; j++) {
        m0 = fmaxf(m0, fmaxf(sc[j][0], sc[j][1]));
        m1 = fmaxf(m1, fmaxf(sc[j][2], sc[j][3]));
    }
    m0 = fmaxf(m0, __shfl_xor_sync(0xffffffffu, m0, 1));
    m0 = fmaxf(m0, __shfl_xor_sync(0xffffffffu, m0, 2));
    m1 = fmaxf(m1, __shfl_xor_sync(0xffffffffu, m1, 1));
    m1 = fmaxf(m1, __shfl_xor_sync(0xffffffffu, m1, 2));
    float l0 = 0.f, l1 = 0.f;
#pragma unroll
    for (int j = 0; j < 32; j++) {
        sc[j][0] = __expf(sc[j][0] - m0); sc[j][1] = __expf(sc[j][1] - m0);
        sc[j][2] = __expf(sc[j][2] - m1); sc[j][3] = __expf(sc[j][3] - m1);
        l0 += sc[j][0] + sc[j][1];
        l1 += sc[j][2] + sc[j][3];
    }
    l0 += __shfl_xor_sync(0xffffffffu, l0, 1); l0 += __shfl_xor_sync(0xffffffffu, l0, 2);
    l1 += __shfl_xor_sync(0xffffffffu, l1, 1); l1 += __shfl_xor_sync(0xffffffffu, l1, 2);
    float il0 = 1.f / l0, il1 = 1.f / l1;

    float*         fo = g_a2f + ((size_t)bh << 16);
    __nv_bfloat16* ho = g_a2h + ((size_t)bh << 16);
    int rlo = bx * 64 + wrow + r0, rhi = rlo + 8;
#pragma unroll
    for (int j = 0; j < 32; j++) {
        int c = j * 8 + kq * 2;
        float a0 = sc[j][0] * il0, a1 = sc[j][1] * il0;
        float b0 = sc[j][2] * il1, b1 = sc[j][3] * il1;
        *(float2*)(fo + (size_t)rlo * 256 + c) = make_float2(a0, a1);
        *(float2*)(fo + (size_t)rhi * 256 + c) = make_float2(b0, b1);
        *(unsigned*)(ho + (size_t)rlo * 256 + c) = packbf(a0, a1);
        *(unsigned*)(ho + (size_t)rhi * 256 + c) = packbf(b0, b1);
    }
}

// ---------------- pipelined bf16 GEMM 128x64 (wm only) ----------------
__global__ __launch_bounds__(256) void tgemm(
    const void* Av, const void* Bv, void* Cv, int Kr,
    int lda, int ldb, int ldc, long sA, long sB, long sC) {
    int bz = blockIdx.z;
    const __nv_bfloat16* Ab = (const __nv_bfloat16*)Av + (size_t)bz * sA;
    const __nv_bfloat16* Bh = (const __nv_bfloat16*)Bv + (size_t)bz * sB;
    __nv_bfloat16*       Cb = (__nv_bfloat16*)Cv + (size_t)bz * sC;

    __shared__ unsigned As[2][128][20];
    __shared__ unsigned Bs[2][64][20];

    int tid = threadIdx.x, lane = tid & 31, w = tid >> 5;
    int wr = w >> 1, wc = w & 1;
    int rowBase = blockIdx.y * 128, colBase = blockIdx.x * 64;
    int r0 = lane >> 2, kq = lane & 3;
    int ar_ = tid >> 1, ah_ = tid & 1;
    int bkp = tid >> 4, bn0 = (tid & 15) * 4;

    float acc[2][4][4];
#pragma unroll
    for (int mi = 0; mi < 2; mi++)
#pragma unroll
        for (int ni = 0; ni < 4; ni++)
#pragma unroll
            for (int q = 0; q < 4; q++) acc[mi][ni][q] = 0.f;

    auto fetchA = [&](int kk, unsigned* pr) {
        const __nv_bfloat16* ap = Ab + (size_t)(rowBase + ar_) * lda + kk + ah_ * 16;
        *(uint4*)&pr[0] = *(const uint4*)ap;
        *(uint4*)&pr[4] = *(const uint4*)(ap + 8);
    };
    auto storeA = [&](const unsigned* pr, int bf) {
        unsigned* dst = &As[bf][ar_][ah_ * 8];
        *(uint4*)&dst[0] = *(const uint4*)&pr[0];
        *(uint4*)&dst[4] = *(const uint4*)&pr[4];
    };
    auto fetchB = [&](int kk, unsigned* pr) {
        const __nv_bfloat16* bp = Bh + (size_t)(kk + 2 * bkp) * ldb + colBase + bn0;
        *(uint2*)&pr[0] = *(const uint2*)bp;
        *(uint2*)&pr[2] = *(const uint2*)(bp + ldb);
    };
    auto storeB = [&](const unsigned* pr, int bf) {
        uint2 r1 = *(const uint2*)&pr[0];
        uint2 r2 = *(const uint2*)&pr[2];
        Bs[bf][bn0 + 0][bkp] = __byte_perm(r1.x, r2.x, 0x5410);
        Bs[bf][bn0 + 1][bkp] = __byte_perm(r1.x, r2.x, 0x7632);
        Bs[bf][bn0 + 2][bkp] = __byte_perm(r1.y, r2.y, 0x5410);
        Bs[bf][bn0 + 3][bkp] = __byte_perm(r1.y, r2.y, 0x7632);
    };

    unsigned prA[8], prB[4];
    fetchA(0, prA); fetchB(0, prB);
    storeA(prA, 0); storeB(prB, 0);
    __syncthreads();

    int buf = 0;
    for (int k0 = 0; k0 < Kr; k0 += 32) {
        bool nxt = (k0 + 32) < Kr;
        if (nxt) { fetchA(k0 + 32, prA); fetchB(k0 + 32, prB); }
#pragma unroll
        for (int ks = 0; ks < 2; ks++) {
            int kb = ks * 8;
            unsigned arf[2][4], brf[4][2];
#pragma unroll
            for (int mi = 0; mi < 2; mi++) {
                int r = wr * 32 + mi * 16 + r0;
                arf[mi][0] = As[buf][r][kb + kq];
                arf[mi][1] = As[buf][r + 8][kb + kq];
                arf[mi][2] = As[buf][r][kb + kq + 4];
                arf[mi][3] = As[buf][r + 8][kb + kq + 4];
            }
#pragma unroll
            for (int ni = 0; ni < 4; ni++) {
                int n = wc * 32 + ni * 8 + r0;
                brf[ni][0] = Bs[buf][n][kb + kq];
                brf[ni][1] = Bs[buf][n][kb + kq + 4];
            }
#pragma unroll
            for (int mi = 0; mi < 2; mi++)
#pragma unroll
                for (int ni = 0; ni < 4; ni++) mma16(acc[mi][ni], arf[mi], brf[ni]);
        }
        if (nxt) { storeA(prA, buf ^ 1); storeB(prB, buf ^ 1); }
        __syncthreads();
        buf ^= 1;
    }

#pragma unroll
    for (int mi = 0; mi < 2; mi++) {
#pragma unroll
        for (int ni = 0; ni < 4; ni++) {
            int rr = rowBase + wr * 32 + mi * 16 + r0;
            int cc = colBase + wc * 32 + ni * 8 + kq * 2;
#pragma unroll
            for (int hf = 0; hf < 2; hf++) {
                int r = rr + hf * 8;
                *(unsigned*)(Cb + (size_t)r * ldc + cc) =
                    packbf(acc[mi][ni][hf * 2], acc[mi][ni][hf * 2 + 1]);
            }
        }
    }
}

// ---------------- big-tile GEMM 128x128 (qkv + final) ----------------
__global__ __launch_bounds__(256) void bgemm(
    const float* __restrict__ Af, const float* __restrict__ Bf, void* Cv,
    int Kr, int lda, int ldb, int ldc, int aMode, int outMode,
    const float* __restrict__ bias, const float* __restrict__ resid,
    const float* __restrict__ gammaP, const float* __restrict__ betaP) {
    extern __shared__ unsigned sm[];
    unsigned* AsB = sm;
    unsigned* BsB = sm + 5120;

    float* Cf = (float*)Cv;

    int tid = threadIdx.x, lane = tid & 31, w = tid >> 5;
    int wr = w >> 2, wc = w & 3;
    int rowBase = blockIdx.y * 128, colBase = blockIdx.x * 128;
    int r0 = lane >> 2, kq = lane & 3;
    int ar_ = tid >> 1, ah_ = tid & 1;
    int bkp = tid >> 4, bk_ = tid & 15;
    int bn0 = bk_ * 8;

    float acc[4][4][4];
#pragma unroll
    for (int mi = 0; mi < 4; mi++)
#pragma unroll
        for (int ni = 0; ni < 4; ni++)
#pragma unroll
            for (int q = 0; q < 4; q++) acc[mi][ni][q] = 0.f;

    auto fetchA = [&](int kk, unsigned* pr) {
        if (aMode == 1) {
            const float* ap = Af + (size_t)(rowBase + ar_) * lda + kk + ah_ * 16;
            *(float4*)&pr[0]  = ((const float4*)ap)[0];
            *(float4*)&pr[4]  = ((const float4*)ap)[1];
            *(float4*)&pr[8]  = ((const float4*)ap)[2];
            *(float4*)&pr[12] = ((const float4*)ap)[3];
        } else {
            int gr = rowBase + ar_;
            int b = gr >> 12, n = gr & 4095;
            int kk2 = kk + ah_ * 16, hh = kk2 >> 6, d = kk2 & 63;
            size_t off = (((size_t)(b * 8 + hh)) * 4096 + n) * 64 + d;
            uint4 u0 = *(const uint4*)(g_outh + off);
            uint4 u1 = *(const uint4*)(g_outh + off + 8);
            uint4 c0 = *(const uint4*)(g_cvh + off);
            uint4 c1 = *(const uint4*)(g_cvh + off + 8);
            unsigned uo[8] = {u0.x, u0.y, u0.z, u0.w, u1.x, u1.y, u1.z, u1.w};
            unsigned co[8] = {c0.x, c0.y, c0.z, c0.w, c1.x, c1.y, c1.z, c1.w};
#pragma unroll
            for (int i = 0; i < 8; i++) {
                float2 fa = unpackbf(uo[i]), fb = unpackbf(co[i]);
                pr[i] = packbf(fa.x + fb.x, fa.y + fb.y);
            }
        }
    };
    auto storeA = [&](int kk, const unsigned* pr, int bf) {
        unsigned* dst = AsB + bf * 2560 + ar_ * 20 + ah_ * 8;
        if (aMode == 1) {
            float mu = g_mu[rowBase + ar_], rsd = g_rs[rowBase + ar_];
            const float* gp = gammaP + kk + ah_ * 16;
            const float* bp = betaP + kk + ah_ * 16;
#pragma unroll
            for (int i = 0; i < 4; i++) {
                float4 a4 = *(const float4*)&pr[i * 4];
                float4 g4 = ((const float4*)gp)[i];
                float4 b4 = ((const float4*)bp)[i];
                float n0v = (a4.x - mu) * rsd * g4.x + b4.x;
                float n1v = (a4.y - mu) * rsd * g4.y + b4.y;
                float n2v = (a4.z - mu) * rsd * g4.z + b4.z;
                float n3v = (a4.w - mu) * rsd * g4.w + b4.w;
                dst[i * 2]     = packbf(n0v, n1v);
                dst[i * 2 + 1] = packbf(n2v, n3v);
            }
        } else {
            *(uint4*)&dst[0] = *(const uint4*)&pr[0];
            *(uint4*)&dst[4] = *(const uint4*)&pr[4];
        }
    };
    auto fetchB = [&](int kk, float* pr) {
        const float* bp = Bf + (size_t)(kk + 2 * bkp) * ldb + colBase + bn0;
        *(float4*)&pr[0]  = ((const float4*)bp)[0];
        *(float4*)&pr[4]  = ((const float4*)bp)[1];
        *(float4*)&pr[8]  = ((const float4*)(bp + ldb))[0];
        *(float4*)&pr[12] = ((const float4*)(bp + ldb))[1];
    };
    auto storeB = [&](const float* pr, int bf) {
        unsigned* base = BsB + bf * 4608;
#pragma unroll
        for (int j = 0; j < 8; j++) {
            int row = bn0 + j;
            base[row * 36 + bkp + bk_] = packbf(pr[j], pr[8 + j]);
        }
    };

    unsigned prA[16]; float prB[16];
    fetchA(0, prA); fetchB(0, prB);
    storeA(0, prA, 0); storeB(prB, 0);
    __syncthreads();

    int buf = 0;
    for (int k0 = 0; k0 < Kr; k0 += 32) {
        bool nxt = (k0 + 32) < Kr;
        if (nxt) { fetchA(k0 + 32, prA); fetchB(k0 + 32, prB); }
        unsigned* As = AsB + buf * 2560;
        unsigned* Bs = BsB + buf * 4608;
#pragma unroll
        for (int ks = 0; ks < 2; ks++) {
            int kb = ks * 8;
            unsigned arf[4][4], brf[4][2];
#pragma unroll
            for (int mi = 0; mi < 4; mi++) {
                int r = wr * 64 + mi * 16 + r0;
                arf[mi][0] = As[r * 20 + kb + kq];
                arf[mi][1] = As[(r + 8) * 20 + kb + kq];
                arf[mi][2] = As[r * 20 + kb + kq + 4];
                arf[mi][3] = As[(r + 8) * 20 + kb + kq + 4];
            }
#pragma unroll
            for (int ni = 0; ni < 4; ni++) {
                int n = wc * 32 + ni * 8 + r0;
                int sh = (n >> 3) & 15;
                brf[ni][0] = Bs[n * 36 + kb + kq + sh];
                brf[ni][1] = Bs[n * 36 + kb + kq + 4 + sh];
            }
#pragma unroll
            for (int mi = 0; mi < 4; mi++)
#pragma unroll
                for (int ni = 0; ni < 4; ni++) mma16(acc[mi][ni], arf[mi], brf[ni]);
        }
        if (nxt) { storeA(k0 + 32, prA, buf ^ 1); storeB(prB, buf ^ 1); }
        __syncthreads();
        buf ^= 1;
    }

#pragma unroll
    for (int mi = 0; mi < 4; mi++) {
#pragma unroll
        for (int ni = 0; ni < 4; ni++) {
            int rr = rowBase + wr * 64 + mi * 16 + r0;
            int cc = colBase + wc * 32 + ni * 8 + kq * 2;
#pragma unroll
            for (int hf = 0; hf < 2; hf++) {
                int r = rr + hf * 8;
                float v0 = acc[mi][ni][hf * 2];
                float v1 = acc[mi][ni][hf * 2 + 1];
                if (outMode == 1) {
                    int which = cc >> 9, inner = cc & 511;
                    int hh = inner >> 6, d = inner & 63;
                    int b = r >> 12, n = r & 4095;
                    size_t dst = (((size_t)(b * 8 + hh)) * 4096 + n) * 64 + d;
                    if (which == 0)      *(unsigned*)(g_q + dst) = packbf(v0 * QSCALE, v1 * QSCALE);
                    else if (which == 1) *(unsigned*)(g_k + dst) = packbf(v0, v1);
                    else                 *(unsigned*)(g_v + dst) = packbf(v0, v1);
                } else {
                    v0 += bias[cc]; v1 += bias[cc + 1];
                    float2 rx = *(const float2*)(resid + (size_t)r * ldc + cc);
                    v0 += rx.x; v1 += rx.y;
                    *(float2*)(Cf + (size_t)r * ldc + cc) = make_float2(v0, v1);
                }
            }
        }
    }
}

// ---------------- NS GEMM core (K-tile 64, wrapped swizzle) ----------------
template <int MODE>
__device__ __forceinline__ void ns_core(
    const __nv_bfloat16* A, const __nv_bfloat16* B, __nv_bfloat16* C,
    float cM, float cA, const __nv_bfloat16* AE, const __nv_bfloat16* AE2) {
    extern __shared__ unsigned sm[];
    unsigned* AsB = sm;
    unsigned* BsB = sm + 9216;

    int tid = threadIdx.x, lane = tid & 31, w = tid >> 5;
    int wr = w >> 2, wc = w & 3;
    int rowBase = blockIdx.y * 128, colBase = blockIdx.x * 128;
    int r0 = lane >> 2, kq = lane & 3;
    int ar_ = tid >> 1, ah_ = tid & 1;
    int bkp = tid >> 4, bk_ = tid & 15;
    int bn0 = bk_ * 8;

    float acc[4][4][4];
#pragma unroll
    for (int mi = 0; mi < 4; mi++)
#pragma unroll
        for (int ni = 0; ni < 4; ni++)
#pragma unroll
            for (int q = 0; q < 4; q++) acc[mi][ni][q] = 0.f;

    auto fetchA = [&](int kk, uint4* pr) {
        const __nv_bfloat16* ap = A + (size_t)(rowBase + ar_) * 256 + kk + ah_ * 32;
#pragma unroll
        for (int i = 0; i < 4; i++) pr[i] = ((const uint4*)ap)[i];
    };
    auto storeA = [&](const uint4* pr, int bf) {
        unsigned* dst = AsB + bf * 4608 + ar_ * 36 + ah_ * 16;
#pragma unroll
        for (int i = 0; i < 4; i++) *(uint4*)&dst[i * 4] = pr[i];
    };
    auto fetchB = [&](int kk, uint4* pr) {
        const __nv_bfloat16* bp = B + (size_t)(kk + 2 * bkp) * 256 + colBase + bn0;
        pr[0] = *(const uint4*)bp;
        pr[1] = *(const uint4*)(bp + 256);
        const __nv_bfloat16* bp2 = bp + 32 * 256;
        pr[2] = *(const uint4*)bp2;
        pr[3] = *(const uint4*)(bp2 + 256);
    };
    auto storeB = [&](const uint4* pr, int bf) {
        unsigned* base = BsB + bf * 4608;
#pragma unroll
        for (int half = 0; half < 2; half++) {
            int p = bkp + 16 * half;
            int col = (p + bk_) & 31;
            unsigned e[4] = {pr[half*2].x, pr[half*2].y, pr[half*2].z, pr[half*2].w};
            unsigned o[4] = {pr[half*2+1].x, pr[half*2+1].y, pr[half*2+1].z, pr[half*2+1].w};
#pragma unroll
            for (int q2 = 0; q2 < 4; q2++) {
                int n = bn0 + 2 * q2;
                base[n * 36 + col]       = __byte_perm(e[q2], o[q2], 0x5410);
                base[(n + 1) * 36 + col] = __byte_perm(e[q2], o[q2], 0x7632);
            }
        }
    };

    uint4 pA[4], pB[4];
    fetchA(0, pA); fetchB(0, pB);
    storeA(pA, 0); storeB(pB, 0);
    __syncthreads();

    int buf = 0;
    for (int k0 = 0; k0 < 256; k0 += 64) {
        bool nxt = k0 < 192;
        if (nxt) { fetchA(k0 + 64, pA); fetchB(k0 + 64, pB); }
        unsigned* As = AsB + buf * 4608;
        unsigned* Bs = BsB + buf * 4608;
#pragma unroll
        for (int ks = 0; ks < 4; ks++) {
            int kb = ks * 8;
            unsigned arf[4][4], brf[4][2];
#pragma unroll
            for (int mi = 0; mi < 4; mi++) {
                int r = wr * 64 + mi * 16 + r0;
                arf[mi][0] = As[r * 36 + kb + kq];
                arf[mi][1] = As[(r + 8) * 36 + kb + kq];
                arf[mi][2] = As[r * 36 + kb + kq + 4];
                arf[mi][3] = As[(r + 8) * 36 + kb + kq + 4];
            }
#pragma unroll
            for (int ni = 0; ni < 4; ni++) {
                int n = wc * 32 + ni * 8 + r0;
                int sh = n >> 3;
                brf[ni][0] = Bs[n * 36 + ((kb + kq + sh) & 31)];
                brf[ni][1] = Bs[n * 36 + ((kb + kq + 4 + sh) & 31)];
            }
#pragma unroll
            for (int mi = 0; mi < 4; mi++)
#pragma unroll
                for (int ni = 0; ni < 4; ni++) mma16(acc[mi][ni], arf[mi], brf[ni]);
        }
        if (nxt) { storeA(pA, buf ^ 1); storeB(pB, buf ^ 1); }
        __syncthreads();
        buf ^= 1;
    }

#pragma unroll
    for (int mi = 0; mi < 4; mi++) {
#pragma unroll
        for (int ni = 0; ni < 4; ni++) {
            int rr = rowBase + wr * 64 + mi * 16 + r0;
            int cc = colBase + wc * 32 + ni * 8 + kq * 2;
#pragma unroll
            for (int hf = 0; hf < 2; hf++) {
                int r = rr + hf * 8;
                float v0, v1;
                if (MODE == 0) {
                    v0 = cM * acc[mi][ni][hf * 2];
                    v1 = cM * acc[mi][ni][hf * 2 + 1];
                    if (AE) {
                        float2 f = unpackbf(*(const unsigned*)(AE + (size_t)r * 256 + cc));
                        v0 += cA * f.x; v1 += cA * f.y;
                    }
                } else if (MODE == 1) {
                    float2 fy  = unpackbf(*(const unsigned*)(AE + (size_t)r * 256 + cc));
                    float2 fy2 = unpackbf(*(const unsigned*)(AE2 + (size_t)r * 256 + cc));
                    v0 = acc[mi][ni][hf * 2]     + 15.f * fy.x - 7.f * fy2.x;
                    v1 = acc[mi][ni][hf * 2 + 1] + 15.f * fy.y - 7.f * fy2.y;
                } else {
                    float2 f = unpackbf(*(const unsigned*)(AE + (size_t)r * 256 + cc));
                    v0 = -0.25f * acc[mi][ni][hf * 2]     + 3.25f * f.x;
                    v1 = -0.25f * acc[mi][ni][hf * 2 + 1] + 3.25f * f.y;
                }
                *(unsigned*)(C + (size_t)r * 256 + cc) = packbf(v0, v1);
            }
        }
    }
}

__global__ __launch_bounds__(256) void ngemm3(
    const __nv_bfloat16* __restrict__ A, const __nv_bfloat16* __restrict__ B,
    __nv_bfloat16* __restrict__ C, float cM, float cA,
    const __nv_bfloat16* __restrict__ AE, int matBase) {
    size_t off = (size_t)(matBase + blockIdx.z) << 16;
    ns_core<0>(A + off, B + off, C + off, cM, cA, AE ? AE + off : nullptr, nullptr);
}

__global__ __launch_bounds__(256) void ngemmR(
    const __nv_bfloat16* __restrict__ Y, const __nv_bfloat16* __restrict__ Y2,
    __nv_bfloat16* __restrict__ R, int matBase) {
    size_t off = (size_t)(matBase + blockIdx.z) << 16;
    ns_core<1>(Y + off, Y2 + off, R + off, 1.f, 0.f, Y + off, Y2 + off);
}

// batched z/y update over [matBase, matBase+count); grid z = count (z only) or 2*count
__global__ __launch_bounds__(256) void ngemmZ(
    const __nv_bfloat16* __restrict__ Zc, __nv_bfloat16* __restrict__ Zo,
    const __nv_bfloat16* __restrict__ Yc, __nv_bfloat16* __restrict__ Yo,
    const __nv_bfloat16* __restrict__ R, int matBase, int count) {
    int idx = blockIdx.z;
    int sel = idx >= count;
    int mat = matBase + (sel ? idx - count : idx);
    size_t off = (size_t)mat << 16;
    const __nv_bfloat16* A = (sel ? Yc : Zc) + off;
    __nv_bfloat16*       C = (sel ? Yo : Zo) + off;
    ns_core<2>(A, R + off, C, 0.f, 0.f, A, nullptr);
}

// ---------------- flash attn3 @ v, split-K x4 (register P-fragments) ----------------
__global__ __launch_bounds__(128) void k_flashs() {
    int rt = blockIdx.x, bh = blockIdx.y, sk = blockIdx.z;
    extern __shared__ unsigned sm[];
    unsigned* Qs  = sm;
    unsigned* Ks0 = sm + 2304;
    unsigned* Vt0 = sm + 6912;
    const __nv_bfloat16* qlp = g_ql + (size_t)bh * 16384 + (size_t)rt * 64 * 64;
    const __nv_bfloat16* kp  = g_k + ((size_t)bh << 18);
    const __nv_bfloat16* vp  = g_v + ((size_t)bh << 18);
    int tid = threadIdx.x, lane = tid & 31, w = tid >> 5;
    int r0 = lane >> 2, kq = lane & 3;
    int wrow = w * 16;
    int kr_ = tid >> 1, kh_ = tid & 1;

    auto fetchK = [&](int n0, uint4* pk) {
        const __nv_bfloat16* ap = kp + (size_t)(n0 + kr_) * 64 + kh_ * 32;
#pragma unroll
        for (int i = 0; i < 4; i++) pk[i] = ((const uint4*)ap)[i];
    };
    auto storeK = [&](const uint4* pk, int bf) {
        unsigned* dst = Ks0 + bf * 2304 + kr_ * 36 + kh_ * 16;
#pragma unroll
        for (int i = 0; i < 4; i++) *(uint4*)&dst[i * 4] = pk[i];
    };
    auto fetchV = [&](int n0, uint4* pv) {
#pragma unroll
        for (int it = 0; it < 2; it++) {
            int i = tid + it * 128;
            int sp = i >> 3, dg = i & 7;
            const __nv_bfloat16* ap = vp + (size_t)(n0 + 2 * sp) * 64 + dg * 8;
            pv[it * 2]     = *(const uint4*)ap;
            pv[it * 2 + 1] = *(const uint4*)(ap + 64);
        }
    };
    auto storeV = [&](const uint4* pv, int bf) {
        unsigned* Vt = Vt0 + bf * 2304;
#pragma unroll
        for (int it = 0; it < 2; it++) {
            int i = tid + it * 128;
            int sp = i >> 3, dg = i & 7;
            unsigned av[4] = {pv[it*2].x, pv[it*2].y, pv[it*2].z, pv[it*2].w};
            unsigned bv[4] = {pv[it*2+1].x, pv[it*2+1].y, pv[it*2+1].z, pv[it*2+1].w};
#pragma unroll
            for (int q2 = 0; q2 < 4; q2++) {
                int d0 = dg * 8 + q2 * 2;
                Vt[d0 * 36 + sp]       = __byte_perm(av[q2], bv[q2], 0x5410);
                Vt[(d0 + 1) * 36 + sp] = __byte_perm(av[q2], bv[q2], 0x7632);
            }
        }
    };

    {
        const __nv_bfloat16* ap = qlp + kr_ * 64 + kh_ * 32;
        unsigned* dst = &Qs[kr_ * 36 + kh_ * 16];
#pragma unroll
        for (int i = 0; i < 4; i++) *(uint4*)&dst[i * 4] = ((const uint4*)ap)[i];
    }
    int nBeg = sk * 1024, nEnd = nBeg + 1024;
    uint4 pk[4], pv[4];
    fetchK(nBeg, pk); fetchV(nBeg, pv);
    storeK(pk, 0); storeV(pv, 0);
    __syncthreads();

    float O[8][4];
#pragma unroll
    for (int j = 0; j < 8; j++)
#pragma unroll
        for (int q = 0; q < 4; q++) O[j][q] = 0.f;
    float m0 = -1e30f, m1 = -1e30f, l0 = 0.f, l1 = 0.f;

    int buf = 0;
    for (int n0 = nBeg; n0 < nEnd; n0 += 64) {
        bool nxt = (n0 + 64) < nEnd;
        if (nxt) { fetchK(n0 + 64, pk); fetchV(n0 + 64, pv); }
        unsigned* Ks = Ks0 + buf * 2304;
        unsigned* Vt = Vt0 + buf * 2304;

        float sc[8][4];
#pragma unroll
        for (int j = 0; j < 8; j++)
#pragma unroll
            for (int q = 0; q < 4; q++) sc[j][q] = 0.f;
#pragma unroll
        for (int ks = 0; ks < 4; ks++) {
            int kb = ks * 8;
            unsigned a[4];
            a[0] = Qs[(wrow + r0) * 36 + kb + kq];
            a[1] = Qs[(wrow + r0 + 8) * 36 + kb + kq];
            a[2] = Qs[(wrow + r0) * 36 + kb + kq + 4];
            a[3] = Qs[(wrow + r0 + 8) * 36 + kb + kq + 4];
#pragma unroll
            for (int j = 0; j < 8; j++) {
                unsigned b[2] = { Ks[(j * 8 + r0) * 36 + kb + kq],
                                  Ks[(j * 8 + r0) * 36 + kb + kq + 4] };
                mma16(sc[j], a, b);
            }
        }
        float tm0 = -1e30f, tm1 = -1e30f;
#pragma unroll
        for (int j = 0; j < 8; j++) {
            tm0 = fmaxf(tm0, fmaxf(sc[j][0], sc[j][1]));
            tm1 = fmaxf(tm1, fmaxf(sc[j][2], sc[j][3]));
        }
        tm0 = fmaxf(tm0, __shfl_xor_sync(0xffffffffu, tm0, 1));
        tm0 = fmaxf(tm0, __shfl_xor_sync(0xffffffffu, tm0, 2));
        tm1 = fmaxf(tm1, __shfl_xor_sync(0xffffffffu, tm1, 1));
        tm1 = fmaxf(tm1, __shfl_xor_sync(0xffffffffu, tm1, 2));
        float mn0 = fmaxf(m0, tm0), mn1 = fmaxf(m1, tm1);
        float al0 = __expf(m0 - mn0), al1 = __expf(m1 - mn1);
        float ts0 = 0.f, ts1 = 0.f;
#pragma unroll
        for (int j = 0; j < 8; j++) {
            sc[j][0] = __expf(sc[j][0] - mn0); sc[j][1] = __expf(sc[j][1] - mn0);
            sc[j][2] = __expf(sc[j][2] - mn1); sc[j][3] = __expf(sc[j][3] - mn1);
            ts0 += sc[j][0] + sc[j][1];
            ts1 += sc[j][2] + sc[j][3];
        }
        ts0 += __shfl_xor_sync(0xffffffffu, ts0, 1); ts0 += __shfl_xor_sync(0xffffffffu, ts0, 2);
        ts1 += __shfl_xor_sync(0xffffffffu, ts1, 1); ts1 += __shfl_xor_sync(0xffffffffu, ts1, 2);
        l0 = l0 * al0 + ts0; l1 = l1 * al1 + ts1;
        m0 = mn0; m1 = mn1;
#pragma unroll
        for (int j = 0; j < 8; j++) {
            O[j][0] *= al0; O[j][1] *= al0; O[j][2] *= al1; O[j][3] *= al1;
        }
#pragma unroll
        for (int ks = 0; ks < 4; ks++) {
            unsigned a[4];
            a[0] = packbf(sc[2*ks][0],   sc[2*ks][1]);
            a[1] = packbf(sc[2*ks][2],   sc[2*ks][3]);
            a[2] = packbf(sc[2*ks+1][0], sc[2*ks+1][1]);
            a[3] = packbf(sc[2*ks+1][2], sc[2*ks+1][3]);
            int kb = ks * 8;
#pragma unroll
            for (int j = 0; j < 8; j++) {
                unsigned b[2] = { Vt[(j * 8 + r0) * 36 + kb + kq],
                                  Vt[(j * 8 + r0) * 36 + kb + kq + 4] };
                mma16(O[j], a, b);
            }
        }
        if (nxt) { storeK(pk, buf ^ 1); storeV(pv, buf ^ 1); }
        __syncthreads();
        buf ^= 1;
    }

    float* op = g_fO + ((((size_t)bh * 4 + rt) * 4 + sk) << 12);
#pragma unroll
    for (int j = 0; j < 8; j++) {
        int c = j * 8 + kq * 2;
        op[(wrow + r0) * 64 + c]         = O[j][0];
        op[(wrow + r0) * 64 + c + 1]     = O[j][1];
        op[(wrow + r0 + 8) * 64 + c]     = O[j][2];
        op[(wrow + r0 + 8) * 64 + c + 1] = O[j][3];
    }
    if (kq == 0) {
        int base = (((bh * 4 + rt) * 4) + sk) * 64;
        g_fm[base + wrow + r0]     = m0; g_fl[base + wrow + r0]     = l0;
        g_fm[base + wrow + r0 + 8] = m1; g_fl[base + wrow + r0 + 8] = l1;
    }
}

__global__ void k_fmerge() {
    int bhrt = blockIdx.x, t = threadIdx.x;
    int r = t >> 2, cg = (t & 3) * 16;
    float mv[4], lv[4];
    float M = -1e30f;
#pragma unroll
    for (int sk = 0; sk < 4; sk++) {
        mv[sk] = g_fm[(bhrt * 4 + sk) * 64 + r];
        lv[sk] = g_fl[(bhrt * 4 + sk) * 64 + r];
        M = fmaxf(M, mv[sk]);
    }
    float co[4], L = 0.f;
#pragma unroll
    for (int sk = 0; sk < 4; sk++) { co[sk] = __expf(mv[sk] - M); L += lv[sk] * co[sk]; }
    float inv = 1.f / L;
    int bh = bhrt >> 2, rt = bhrt & 3;
    __nv_bfloat16* op = g_a3v + (size_t)bh * 16384 + rt * 4096 + r * 64 + cg;
#pragma unroll
    for (int cp = 0; cp < 8; cp++) {
        float o0 = 0.f, o1 = 0.f;
#pragma unroll
        for (int sk = 0; sk < 4; sk++) {
            const float* P = g_fO + (((size_t)(bhrt * 4 + sk)) << 12) + r * 64 + cg + cp * 2;
            o0 += co[sk] * P[0];
            o1 += co[sk] * P[1];
        }
        *(unsigned*)(op + cp * 2) = packbf(o0 * inv, o1 * inv);
    }
}

// ---------------- fused attn1, chunked online-softmax, register P ----------------
__global__ __launch_bounds__(256, 2) void k_attn1() {
    int bx = blockIdx.x, bh = blockIdx.y;
    extern __shared__ unsigned sm[];
    unsigned* Qs = sm;
    unsigned* SH = sm + 4608;
    const __nv_bfloat16* qp  = g_q + ((size_t)bh << 18) + (size_t)bx * 128 * 64;
    const __nv_bfloat16* klp = g_kl + (size_t)bh * 16384;
    const __nv_bfloat16* wp  = g_wm + (size_t)bh * 16384;
    int tid = threadIdx.x, lane = tid & 31, w = tid >> 5;
    int r0 = lane >> 2, kq = lane & 3;
    int wrow = w * 16;

    {
        int r = tid >> 1, h = tid & 1;
        const __nv_bfloat16* ap = qp + r * 64 + h * 32;
        unsigned* dst = &Qs[r * 36 + h * 16];
#pragma unroll
        for (int i = 0; i < 4; i++) *(uint4*)&dst[i * 4] = ((const uint4*)ap)[i];
    }

    float O[8][4];
#pragma unroll
    for (int j = 0; j < 8; j++)
#pragma unroll
        for (int q = 0; q < 4; q++) O[j][q] = 0.f;
    float m0 = -1e30f, m1 = -1e30f, l0 = 0.f, l1 = 0.f;

    for (int ch = 0; ch < 2; ch++) {
        __syncthreads();
        {
            int r = tid >> 1, h = tid & 1;
            const __nv_bfloat16* ap = klp + (size_t)(ch * 128 + r) * 64 + h * 32;
            unsigned* dst = &SH[r * 36 + h * 16];
#pragma unroll
            for (int i = 0; i < 4; i++) *(uint4*)&dst[i * 4] = ((const uint4*)ap)[i];
        }
        __syncthreads();

        float sc[16][4];
#pragma unroll
        for (int j = 0; j < 16; j++)
#pragma unroll
            for (int q = 0; q < 4; q++) sc[j][q] = 0.f;
#pragma unroll
        for (int ks = 0; ks < 4; ks++) {
            int kb = ks * 8;
            unsigned a[4];
            a[0] = Qs[(wrow + r0) * 36 + kb + kq];
            a[1] = Qs[(wrow + r0 + 8) * 36 + kb + kq];
            a[2] = Qs[(wrow + r0) * 36 + kb + kq + 4];
            a[3] = Qs[(wrow + r0 + 8) * 36 + kb + kq + 4];
#pragma unroll
            for (int j = 0; j < 16; j++) {
                unsigned b[2] = { SH[(j * 8 + r0) * 36 + kb + kq],
                                  SH[(j * 8 + r0) * 36 + kb + kq + 4] };
                mma16(sc[j], a, b);
            }
        }
        float tm0 = -1e30f, tm1 = -1e30f;
#pragma unroll
        for (int j = 0; j < 16; j++) {
            tm0 = fmaxf(tm0, fmaxf(sc[j][0], sc[j][1]));
            tm1 = fmaxf(tm1, fmaxf(sc[j][2], sc[j][3]));
        }
        tm0 = fmaxf(tm0, __shfl_xor_sync(0xffffffffu, tm0, 1));
        tm0 = fmaxf(tm0, __shfl_xor_sync(0xffffffffu, tm0, 2));
        tm1 = fmaxf(tm1, __shfl_xor_sync(0xffffffffu, tm1, 1));
        tm1 = fmaxf(tm1, __shfl_xor_sync(0xffffffffu, tm1, 2));
        float mn0 = fmaxf(m0, tm0), mn1 = fmaxf(m1, tm1);
        float al0 = __expf(m0 - mn0), al1 = __expf(m1 - mn1);
        float ts0 = 0.f, ts1 = 0.f;
#pragma unroll
        for (int j = 0; j < 16; j++) {
            sc[j][0] = __expf(sc[j][0] - mn0); sc[j][1] = __expf(sc[j][1] - mn0);
            sc[j][2] = __expf(sc[j][2] - mn1); sc[j][3] = __expf(sc[j][3] - mn1);
            ts0 += sc[j][0] + sc[j][1];
            ts1 += sc[j][2] + sc[j][3];
        }
        ts0 += __shfl_xor_sync(0xffffffffu, ts0, 1); ts0 += __shfl_xor_sync(0xffffffffu, ts0, 2);
        ts1 += __shfl_xor_sync(0xffffffffu, ts1, 1); ts1 += __shfl_xor_sync(0xffffffffu, ts1, 2);
        l0 = l0 * al0 + ts0; l1 = l1 * al1 + ts1;
        m0 = mn0; m1 = mn1;
#pragma unroll
        for (int j = 0; j < 8; j++) {
            O[j][0] *= al0; O[j][1] *= al0; O[j][2] *= al1; O[j][3] *= al1;
        }

        __syncthreads();
        {
#pragma unroll
            for (int it = 0; it < 2; it++) {
                int i = tid + it * 256;
                int sp = i >> 3, dg = i & 7;
                const __nv_bfloat16* ap = wp + (size_t)(ch * 128 + 2 * sp) * 64 + dg * 8;
                uint4 ua = *(const uint4*)ap;
                uint4 ub = *(const uint4*)(ap + 64);
                unsigned av[4] = {ua.x, ua.y, ua.z, ua.w};
                unsigned bv[4] = {ub.x, ub.y, ub.z, ub.w};
#pragma unroll
                for (int q2 = 0; q2 < 4; q2++) {
                    int d0 = dg * 8 + q2 * 2;
                    SH[d0 * 68 + sp]       = __byte_perm(av[q2], bv[q2], 0x5410);
                    SH[(d0 + 1) * 68 + sp] = __byte_perm(av[q2], bv[q2], 0x7632);
                }
            }
        }
        __syncthreads();

#pragma unroll
        for (int ks = 0; ks < 8; ks++) {
            unsigned a[4];
            a[0] = packbf(sc[2*ks][0],   sc[2*ks][1]);
            a[1] = packbf(sc[2*ks][2],   sc[2*ks][3]);
            a[2] = packbf(sc[2*ks+1][0], sc[2*ks+1][1]);
            a[3] = packbf(sc[2*ks+1][2], sc[2*ks+1][3]);
            int kb = ks * 8;
#pragma unroll
            for (int j = 0; j < 8; j++) {
                unsigned b[2] = { SH[(j * 8 + r0) * 68 + kb + kq],
                                  SH[(j * 8 + r0) * 68 + kb + kq + 4] };
                mma16(O[j], a, b);
            }
        }
    }

    float il0 = 1.f / l0, il1 = 1.f / l1;
    __nv_bfloat16* op = g_outh + ((size_t)bh << 18) + (size_t)bx * 128 * 64;
#pragma unroll
    for (int j = 0; j < 8; j++) {
        *(unsigned*)(op + (wrow + r0) * 64 + j * 8 + kq * 2)     = packbf(O[j][0] * il0, O[j][1] * il0);
        *(unsigned*)(op + (wrow + r0 + 8) * 64 + j * 8 + kq * 2) = packbf(O[j][2] * il1, O[j][3] * il1);
    }
}

// ---------------- host orchestration ----------------
extern "C" void kernel_launch(void* const* d_in, const int* in_sizes, int n_in,
                              void* d_out, int out_size) {
    const float* x      = (const float*)d_in[0];
    const float* gamma  = (const float*)d_in[1];
    const float* beta   = (const float*)d_in[2];
    const float* w_qkv  = (const float*)d_in[3];
    const float* w_out  = (const float*)d_in[4];
    const float* b_out  = (const float*)d_in[5];
    const float* conv_w = (const float*)d_in[6];
    float* out = (float*)d_out;

    void* tp;
    cudaGetSymbolAddress(&tp, g_a2f);  float*         p_a2f = (float*)tp;
    cudaGetSymbolAddress(&tp, g_a2h);  __nv_bfloat16* p_a2h = (__nv_bfloat16*)tp;
    cudaGetSymbolAddress(&tp, g_z);    __nv_bfloat16* p_z   = (__nv_bfloat16*)tp;
    cudaGetSymbolAddress(&tp, g_zn);   __nv_bfloat16* p_zn  = (__nv_bfloat16*)tp;
    cudaGetSymbolAddress(&tp, g_az);   __nv_bfloat16* p_y   = (__nv_bfloat16*)tp;
    cudaGetSymbolAddress(&tp, g_w1);   __nv_bfloat16* p_y2  = (__nv_bfloat16*)tp;
    cudaGetSymbolAddress(&tp, g_w2);   __nv_bfloat16* p_r   = (__nv_bfloat16*)tp;
    cudaGetSymbolAddress(&tp, g_a3v);  __nv_bfloat16* p_a3v = (__nv_bfloat16*)tp;
    cudaGetSymbolAddress(&tp, g_wm);   __nv_bfloat16* p_wm  = (__nv_bfloat16*)tp;

    static cudaStream_t s2 = nullptr;
    static cudaEvent_t evF = nullptr, evZ = nullptr, evJ = nullptr;
    if (!s2) {
        cudaStreamCreateWithFlags(&s2, cudaStreamNonBlocking);
        cudaEventCreateWithFlags(&evF, cudaEventDisableTiming);
        cudaEventCreateWithFlags(&evZ, cudaEventDisableTiming);
        cudaEventCreateWithFlags(&evJ, cudaEventDisableTiming);
    }

    cudaFuncSetAttribute(k_flashs, cudaFuncAttributeMaxDynamicSharedMemorySize, 46080);
    cudaFuncSetAttribute(k_attn1,  cudaFuncAttributeMaxDynamicSharedMemorySize, 36864);
    cudaFuncSetAttribute(k_score2, cudaFuncAttributeMaxDynamicSharedMemorySize, 46080);
    cudaFuncSetAttribute(bgemm,    cudaFuncAttributeMaxDynamicSharedMemorySize, 57344);
    cudaFuncSetAttribute(ngemm3,   cudaFuncAttributeMaxDynamicSharedMemorySize, 73728);
    cudaFuncSetAttribute(ngemmR,   cudaFuncAttributeMaxDynamicSharedMemorySize, 73728);
    cudaFuncSetAttribute(ngemmZ,   cudaFuncAttributeMaxDynamicSharedMemorySize, 73728);

    k_lnstats<<<Bb * Nn, 256>>>(x);

    // qkv = LN(x) @ w_qkv -> scatter bf16 q/k/v
    bgemm<<<dim3(12, 128, 1), 256, 57344>>>(x, w_qkv, nullptr, 512, 512, 1536, 1536,
        1, 1, nullptr, nullptr, gamma, beta);

    k_land<<<(2 * BHc * Mm * 32) / 256, 256>>>();

    // ---- fork: flash chain + conv + NS tail-half on s2 ----
    cudaEventRecord(evF, 0);
    cudaStreamWaitEvent(s2, evF, 0);
    k_flashs<<<dim3(4, 32, 4), 128, 46080, s2>>>();
    k_fmerge<<<128, 256, 0, s2>>>();
    k_conv2<<<dim3(32, 32), 256, 0, s2>>>(conv_w);

    // main chain: scores -> sums -> z0
    k_score2<<<dim3(4, 32), 128, 46080>>>();
    k_sums<<<BHc, 256>>>(p_a2f);
    k_z0<<<(BHc * Mm * Mm / 2) / 256, 256>>>();
    cudaEventRecord(evZ, 0);
    cudaStreamWaitEvent(s2, evZ, 0);

    // Newton-Schulz split: main does matrices [0,24), s2 does [24,32)
    auto ns_half = [&](cudaStream_t st, int base, int cnt) {
        ngemm3<<<dim3(2, 2, cnt), 256, 73728, st>>>(p_a2h, p_z, p_y, 1.f, 0.f, nullptr, base);
        __nv_bfloat16* zc = p_z;  __nv_bfloat16* zo = p_zn;
        __nv_bfloat16* yc = p_y;  __nv_bfloat16* yo = p_a2h;
        for (int it = 0; it < 6; it++) {
            ngemm3<<<dim3(2, 2, cnt), 256, 73728, st>>>(yc, yc, p_y2, 1.f, 0.f, nullptr, base);
            ngemmR<<<dim3(2, 2, cnt), 256, 73728, st>>>(yc, p_y2, p_r, base);
            if (it < 5) {
                ngemmZ<<<dim3(2, 2, 2 * cnt), 256, 73728, st>>>(zc, zo, yc, yo, p_r, base, cnt);
                __nv_bfloat16* t;
                t = zc; zc = zo; zo = t;
                t = yc; yc = yo; yo = t;
            } else {
                ngemmZ<<<dim3(2, 2, cnt), 256, 73728, st>>>(zc, zo, yc, yo, p_r, base, cnt);
                __nv_bfloat16* t = zc; zc = zo; zo = t;
            }
        }
    };
    ns_half(0, 0, 24);
    ns_half(s2, 24, 8);
    cudaEventRecord(evJ, s2);

    // ---- join ----
    cudaStreamWaitEvent(0, evJ, 0);

    // wm = Z @ a3v   (final Z lives in g_z for both halves: 6 swaps)
    tgemm<<<dim3(1, 2, 32), 256>>>(p_z, p_a3v, p_wm, 256, 256, 64, 64,
        (long)Mm * Mm, (long)Mm * Dd, (long)Mm * Dd);

    // fused attn1 -> outh
    k_attn1<<<dim3(32, 32), 256, 36864>>>();

    // final: out = (merge(outh)+cvh) @ w_out + b_out + x
    bgemm<<<dim3(4, 128, 1), 256, 57344>>>(nullptr, w_out, out, 512, 512, 512, 512,
        2, 2, b_out, x, nullptr, nullptr);
}

// round 15
// speedup vs baseline: 1.0159x; 1.0159x over previous
#include <cuda_runtime.h>
#include <cuda_bf16.h>
#include <cstddef>

#define Bb 4
#define Nn 4096
#define DIMV 512
#define Hh 8
#define Dd 64
#define Mm 256
#define BHc 32
#define QSCALE 0.125f

// ---------------- scratch ----------------
__device__ __nv_bfloat16 g_q   [BHc*Nn*Dd];
__device__ __nv_bfloat16 g_k   [BHc*Nn*Dd];
__device__ __nv_bfloat16 g_v   [BHc*Nn*Dd];
__device__ __nv_bfloat16 g_ql  [BHc*Mm*Dd];
__device__ __nv_bfloat16 g_kl  [BHc*Mm*Dd];
__device__ __nv_bfloat16 g_a2h [BHc*Mm*Mm];   // A2; reused as y ping buffer
__device__ __nv_bfloat16 g_z   [BHc*Mm*Mm];
__device__ __nv_bfloat16 g_zn  [BHc*Mm*Mm];
__device__ __nv_bfloat16 g_az  [BHc*Mm*Mm];   // y
__device__ __nv_bfloat16 g_w1  [BHc*Mm*Mm];   // y^2
__device__ __nv_bfloat16 g_w2  [BHc*Mm*Mm];   // r
__device__ __nv_bfloat16 g_a3v [BHc*Mm*Dd];
__device__ __nv_bfloat16 g_wm  [BHc*Mm*Dd];
__device__ __nv_bfloat16 g_outh[BHc*Nn*Dd];
__device__ __nv_bfloat16 g_cvh [BHc*Nn*Dd];
__device__ float g_mu[Bb*Nn];
__device__ float g_rs[Bb*Nn];
__device__ float g_cs[BHc*Mm];   // per-column sums of softmaxed a2
__device__ float g_ms2;
__device__ float g_fO[BHc*4*4*4096];
__device__ float g_fm[BHc*4*4*64];
__device__ float g_fl[BHc*4*4*64];

__device__ __forceinline__ unsigned packbf(float a, float b) {
    __nv_bfloat162 t = __floats2bfloat162_rn(a, b);
    return *reinterpret_cast<unsigned*>(&t);
}
__device__ __forceinline__ float2 unpackbf(unsigned u) {
    __nv_bfloat162 t = *reinterpret_cast<__nv_bfloat162*>(&u);
    return make_float2(__bfloat162float(t.x), __bfloat162float(t.y));
}
__device__ __forceinline__ void mma16(float* c, const unsigned* a, const unsigned* b) {
    asm volatile("mma.sync.aligned.m16n8k16.row.col.f32.bf16.bf16.f32 "
                 "{%0,%1,%2,%3},{%4,%5,%6,%7},{%8,%9},{%0,%1,%2,%3};"
                 : "+f"(c[0]), "+f"(c[1]), "+f"(c[2]), "+f"(c[3])
                 : "r"(a[0]), "r"(a[1]), "r"(a[2]), "r"(a[3]), "r"(b[0]), "r"(b[1]));
}

// ---------------- small kernels ----------------
__global__ void k_lnstats(const float* __restrict__ x) {
    int r = blockIdx.x, t = threadIdx.x;
    if (r == 0 && t == 0) g_ms2 = 0.f;
    if (r < BHc) g_cs[r * 256 + t] = 0.f;
    const float* xp = x + (size_t)r * DIMV;
    float v0 = xp[t], v1 = xp[t + 256];
    __shared__ float red[256];
    red[t] = v0 + v1; __syncthreads();
    for (int s = 128; s; s >>= 1) { if (t < s) red[t] += red[t + s]; __syncthreads(); }
    float mean = red[0] * (1.f / 512.f);
    __syncthreads();
    float d0 = v0 - mean, d1 = v1 - mean;
    red[t] = d0 * d0 + d1 * d1; __syncthreads();
    for (int s = 128; s; s >>= 1) { if (t < s) red[t] += red[t + s]; __syncthreads(); }
    if (t == 0) { g_mu[r] = mean; g_rs[r] = rsqrtf(red[0] * (1.f / 512.f) + 1e-5f); }
}

__global__ void k_land() {
    int idx = blockIdx.x * 256 + threadIdx.x;
    int sel = idx >= (BHc * Mm * 32);
    int e = idx & (BHc * Mm * 32 - 1);
    int bh = e >> 13, j = (e >> 5) & 255, dp = e & 31;
    const __nv_bfloat16* src = sel ? g_k : g_q;
    const __nv_bfloat16* p = src + ((size_t)bh * 4096 + j * 16) * 64 + dp * 2;
    float s0 = 0.f, s1 = 0.f;
#pragma unroll
    for (int t = 0; t < 16; t++) {
        float2 f = unpackbf(*(const unsigned*)(p + t * 64));
        s0 += f.x; s1 += f.y;
    }
    __nv_bfloat16* dst = sel ? g_kl : g_ql;
    *(unsigned*)(dst + (size_t)bh * 16384 + j * 64 + dp * 2) =
        packbf(s0 * (1.f / 16.f), s1 * (1.f / 16.f));
}

// max column-sum from the tiny g_cs array
__global__ void k_sums() {
    int mat = blockIdx.x, t = threadIdx.x;
    float cs = g_cs[mat * 256 + t];
    __shared__ float red[256];
    red[t] = cs; __syncthreads();
    for (int s = 128; s; s >>= 1) { if (t < s) red[t] = fmaxf(red[t], red[t + s]); __syncthreads(); }
    if (!t) atomicMax((int*)&g_ms2, __float_as_int(red[0]));
}

// z0 = a2h^T / ms2  (bf16 source)
__global__ void k_z0() {
    int p = blockIdx.x * 256 + threadIdx.x;
    float inv = 1.f / g_ms2;
    int mat = p >> 15, rem = p & 32767;
    int r = rem >> 7, cp = (rem & 127) * 2;
    const __nv_bfloat16* A = g_a2h + ((size_t)mat << 16);
    float t0 = __bfloat162float(A[(size_t)cp * 256 + r]);
    float t1 = __bfloat162float(A[(size_t)(cp + 1) * 256 + r]);
    *(unsigned*)(g_z + ((size_t)mat << 16) + (size_t)r * 256 + cp) = packbf(t0 * inv, t1 * inv);
}

__global__ void k_conv2(const float* __restrict__ w) {
    int nt = blockIdx.x, bh = blockIdx.y;
    __shared__ float vs[160][64];
    const __nv_bfloat16* vp = g_v + ((size_t)bh << 18);
    int n0 = nt * 128;
    for (int i = threadIdx.x; i < 160 * 8; i += 256) {
        int r = i >> 3, g = i & 7;
        int n = n0 - 16 + r;
        if (n >= 0 && n < 4096) {
            uint4 u = *(const uint4*)(vp + (size_t)n * 64 + g * 8);
            float2 f0 = unpackbf(u.x), f1 = unpackbf(u.y), f2 = unpackbf(u.z), f3 = unpackbf(u.w);
            vs[r][g * 8 + 0] = f0.x; vs[r][g * 8 + 1] = f0.y;
            vs[r][g * 8 + 2] = f1.x; vs[r][g * 8 + 3] = f1.y;
            vs[r][g * 8 + 4] = f2.x; vs[r][g * 8 + 5] = f2.y;
            vs[r][g * 8 + 6] = f3.x; vs[r][g * 8 + 7] = f3.y;
        } else {
#pragma unroll
            for (int q = 0; q < 8; q++) vs[r][g * 8 + q] = 0.f;
        }
    }
    __syncthreads();
    int h = bh & 7;
    float wr[33];
#pragma unroll
    for (int t = 0; t < 33; t++) wr[t] = w[h * 33 + t];
    int dp = threadIdx.x & 31, nl = threadIdx.x >> 5;
    for (int p = 0; p < 16; p++) {
        int n = nl + p * 8;
        float a0 = 0.f, a1 = 0.f;
#pragma unroll
        for (int t = 0; t < 33; t++) {
            a0 += wr[t] * vs[n + t][dp * 2];
            a1 += wr[t] * vs[n + t][dp * 2 + 1];
        }
        *(unsigned*)(g_cvh + ((size_t)bh * 4096 + n0 + n) * 64 + dp * 2) = packbf(a0, a1);
    }
}

// ---------------- fused scores+softmax + column-sum, 64 rows/block ----------------
__global__ __launch_bounds__(128) void k_score2() {
    int bx = blockIdx.x, bh = blockIdx.y;
    extern __shared__ unsigned sm[];
    unsigned* Qs  = sm;
    unsigned* KLs = sm + 2304;
    __shared__ float csum[256];
    const __nv_bfloat16* qlp = g_ql + (size_t)bh * 16384 + (size_t)bx * 64 * 64;
    const __nv_bfloat16* klp = g_kl + (size_t)bh * 16384;
    int tid = threadIdx.x, lane = tid & 31, w = tid >> 5;
    int r0 = lane >> 2, kq = lane & 3;
    int wrow = w * 16;

    csum[tid] = 0.f; csum[tid + 128] = 0.f;
    {
        int r = tid >> 1, h = tid & 1;
        const __nv_bfloat16* ap = qlp + r * 64 + h * 32;
        unsigned* dst = &Qs[r * 36 + h * 16];
#pragma unroll
        for (int i = 0; i < 4; i++) *(uint4*)&dst[i * 4] = ((const uint4*)ap)[i];
    }
#pragma unroll
    for (int rr = 0; rr < 2; rr++) {
        int r = tid + rr * 128;
        const __nv_bfloat16* ap = klp + r * 64;
        unsigned* dst = &KLs[r * 36];
#pragma unroll
        for (int i = 0; i < 8; i++) *(uint4*)&dst[i * 4] = ((const uint4*)ap)[i];
    }
    __syncthreads();

    float sc[32][4];
#pragma unroll
    for (int j = 0; j < 32; j++)
#pragma unroll
        for (int q = 0; q < 4; q++) sc[j][q] = 0.f;
#pragma unroll
    for (int ks = 0; ks < 4; ks++) {
        int kb = ks * 8;
        unsigned a[4];
        a[0] = Qs[(wrow + r0) * 36 + kb + kq];
        a[1] = Qs[(wrow + r0 + 8) * 36 + kb + kq];
        a[2] = Qs[(wrow + r0) * 36 + kb + kq + 4];
        a[3] = Qs[(wrow + r0 + 8) * 36 + kb + kq + 4];
#pragma unroll
        for (int j = 0; j < 32; j++) {
            unsigned b[2] = { KLs[(j * 8 + r0) * 36 + kb + kq],
                              KLs[(j * 8 + r0) * 36 + kb + kq + 4] };
            mma16(sc[j], a, b);
        }
    }
    float m0 = -1e30f, m1 = -1e30f;
#pragma unroll
    for (int j = 0; j < 32; j++) {
        m0 = fmaxf(m0, fmaxf(sc[j][0], sc[j][1]));
        m1 = fmaxf(m1, fmaxf(sc[j][2], sc[j][3]));
    }
    m0 = fmaxf(m0, __shfl_xor_sync(0xffffffffu, m0, 1));
    m0 = fmaxf(m0, __shfl_xor_sync(0xffffffffu, m0, 2));
    m1 = fmaxf(m1, __shfl_xor_sync(0xffffffffu, m1, 1));
    m1 = fmaxf(m1, __shfl_xor_sync(0xffffffffu, m1, 2));
    float l0 = 0.f, l1 = 0.f;
#pragma unroll
    for (int j = 0; j < 32; j++) {
        sc[j][0] = __expf(sc[j][0] - m0); sc[j][1] = __expf(sc[j][1] - m0);
        sc[j][2] = __expf(sc[j][2] - m1); sc[j][3] = __expf(sc[j][3] - m1);
        l0 += sc[j][0] + sc[j][1];
        l1 += sc[j][2] + sc[j][3];
    }
    l0 += __shfl_xor_sync(0xffffffffu, l0, 1); l0 += __shfl_xor_sync(0xffffffffu, l0, 2);
    l1 += __shfl_xor_sync(0xffffffffu, l1, 1); l1 += __shfl_xor_sync(0xffffffffu, l1, 2);
    float il0 = 1.f / l0, il1 = 1.f / l1;

    __nv_bfloat16* ho = g_a2h + ((size_t)bh << 16);
    int rlo = bx * 64 + wrow + r0, rhi = rlo + 8;
#pragma unroll
    for (int j = 0; j < 32; j++) {
        int c = j * 8 + kq * 2;
        float a0 = sc[j][0] * il0, a1 = sc[j][1] * il0;
        float b0 = sc[j][2] * il1, b1 = sc[j][3] * il1;
        *(unsigned*)(ho + (size_t)rlo * 256 + c) = packbf(a0, a1);
        *(unsigned*)(ho + (size_t)rhi * 256 + c) = packbf(b0, b1);
        atomicAdd(&csum[c],     a0 + b0);
        atomicAdd(&csum[c + 1], a1 + b1);
    }
    __syncthreads();
    atomicAdd(&g_cs[bh * 256 + tid],       csum[tid]);
    atomicAdd(&g_cs[bh * 256 + tid + 128], csum[tid + 128]);
}

// ---------------- pipelined bf16 GEMM 128x64 (wm only) ----------------
__global__ __launch_bounds__(256) void tgemm(
    const void* Av, const void* Bv, void* Cv, int Kr,
    int lda, int ldb, int ldc, long sA, long sB, long sC) {
    int bz = blockIdx.z;
    const __nv_bfloat16* Ab = (const __nv_bfloat16*)Av + (size_t)bz * sA;
    const __nv_bfloat16* Bh = (const __nv_bfloat16*)Bv + (size_t)bz * sB;
    __nv_bfloat16*       Cb = (__nv_bfloat16*)Cv + (size_t)bz * sC;

    __shared__ unsigned As[2][128][20];
    __shared__ unsigned Bs[2][64][20];

    int tid = threadIdx.x, lane = tid & 31, w = tid >> 5;
    int wr = w >> 1, wc = w & 1;
    int rowBase = blockIdx.y * 128, colBase = blockIdx.x * 64;
    int r0 = lane >> 2, kq = lane & 3;
    int ar_ = tid >> 1, ah_ = tid & 1;
    int bkp = tid >> 4, bn0 = (tid & 15) * 4;

    float acc[2][4][4];
#pragma unroll
    for (int mi = 0; mi < 2; mi++)
#pragma unroll
        for (int ni = 0; ni < 4; ni++)
#pragma unroll
            for (int q = 0; q < 4; q++) acc[mi][ni][q] = 0.f;

    auto fetchA = [&](int kk, unsigned* pr) {
        const __nv_bfloat16* ap = Ab + (size_t)(rowBase + ar_) * lda + kk + ah_ * 16;
        *(uint4*)&pr[0] = *(const uint4*)ap;
        *(uint4*)&pr[4] = *(const uint4*)(ap + 8);
    };
    auto storeA = [&](const unsigned* pr, int bf) {
        unsigned* dst = &As[bf][ar_][ah_ * 8];
        *(uint4*)&dst[0] = *(const uint4*)&pr[0];
        *(uint4*)&dst[4] = *(const uint4*)&pr[4];
    };
    auto fetchB = [&](int kk, unsigned* pr) {
        const __nv_bfloat16* bp = Bh + (size_t)(kk + 2 * bkp) * ldb + colBase + bn0;
        *(uint2*)&pr[0] = *(const uint2*)bp;
        *(uint2*)&pr[2] = *(const uint2*)(bp + ldb);
    };
    auto storeB = [&](const unsigned* pr, int bf) {
        uint2 r1 = *(const uint2*)&pr[0];
        uint2 r2 = *(const uint2*)&pr[2];
        Bs[bf][bn0 + 0][bkp] = __byte_perm(r1.x, r2.x, 0x5410);
        Bs[bf][bn0 + 1][bkp] = __byte_perm(r1.x, r2.x, 0x7632);
        Bs[bf][bn0 + 2][bkp] = __byte_perm(r1.y, r2.y, 0x5410);
        Bs[bf][bn0 + 3][bkp] = __byte_perm(r1.y, r2.y, 0x7632);
    };

    unsigned prA[8], prB[4];
    fetchA(0, prA); fetchB(0, prB);
    storeA(prA, 0); storeB(prB, 0);
    __syncthreads();

    int buf = 0;
    for (int k0 = 0; k0 < Kr; k0 += 32) {
        bool nxt = (k0 + 32) < Kr;
        if (nxt) { fetchA(k0 + 32, prA); fetchB(k0 + 32, prB); }
#pragma unroll
        for (int ks = 0; ks < 2; ks++) {
            int kb = ks * 8;
            unsigned arf[2][4], brf[4][2];
#pragma unroll
            for (int mi = 0; mi < 2; mi++) {
                int r = wr * 32 + mi * 16 + r0;
                arf[mi][0] = As[buf][r][kb + kq];
                arf[mi][1] = As[buf][r + 8][kb + kq];
                arf[mi][2] = As[buf][r][kb + kq + 4];
                arf[mi][3] = As[buf][r + 8][kb + kq + 4];
            }
#pragma unroll
            for (int ni = 0; ni < 4; ni++) {
                int n = wc * 32 + ni * 8 + r0;
                brf[ni][0] = Bs[buf][n][kb + kq];
                brf[ni][1] = Bs[buf][n][kb + kq + 4];
            }
#pragma unroll
            for (int mi = 0; mi < 2; mi++)
#pragma unroll
                for (int ni = 0; ni < 4; ni++) mma16(acc[mi][ni], arf[mi], brf[ni]);
        }
        if (nxt) { storeA(prA, buf ^ 1); storeB(prB, buf ^ 1); }
        __syncthreads();
        buf ^= 1;
    }

#pragma unroll
    for (int mi = 0; mi < 2; mi++) {
#pragma unroll
        for (int ni = 0; ni < 4; ni++) {
            int rr = rowBase + wr * 32 + mi * 16 + r0;
            int cc = colBase + wc * 32 + ni * 8 + kq * 2;
#pragma unroll
            for (int hf = 0; hf < 2; hf++) {
                int r = rr + hf * 8;
                *(unsigned*)(Cb + (size_t)r * ldc + cc) =
                    packbf(acc[mi][ni][hf * 2], acc[mi][ni][hf * 2 + 1]);
            }
        }
    }
}

// ---------------- big-tile GEMM 128x128 (qkv + final) ----------------
__global__ __launch_bounds__(256) void bgemm(
    const float* __restrict__ Af, const float* __restrict__ Bf, void* Cv,
    int Kr, int lda, int ldb, int ldc, int aMode, int outMode,
    const float* __restrict__ bias, const float* __restrict__ resid,
    const float* __restrict__ gammaP, const float* __restrict__ betaP) {
    extern __shared__ unsigned sm[];
    unsigned* AsB = sm;
    unsigned* BsB = sm + 5120;

    float* Cf = (float*)Cv;

    int tid = threadIdx.x, lane = tid & 31, w = tid >> 5;
    int wr = w >> 2, wc = w & 3;
    int rowBase = blockIdx.y * 128, colBase = blockIdx.x * 128;
    int r0 = lane >> 2, kq = lane & 3;
    int ar_ = tid >> 1, ah_ = tid & 1;
    int bkp = tid >> 4, bk_ = tid & 15;
    int bn0 = bk_ * 8;

    float acc[4][4][4];
#pragma unroll
    for (int mi = 0; mi < 4; mi++)
#pragma unroll
        for (int ni = 0; ni < 4; ni++)
#pragma unroll
            for (int q = 0; q < 4; q++) acc[mi][ni][q] = 0.f;

    auto fetchA = [&](int kk, unsigned* pr) {
        if (aMode == 1) {
            const float* ap = Af + (size_t)(rowBase + ar_) * lda + kk + ah_ * 16;
            *(float4*)&pr[0]  = ((const float4*)ap)[0];
            *(float4*)&pr[4]  = ((const float4*)ap)[1];
            *(float4*)&pr[8]  = ((const float4*)ap)[2];
            *(float4*)&pr[12] = ((const float4*)ap)[3];
        } else {
            int gr = rowBase + ar_;
            int b = gr >> 12, n = gr & 4095;
            int kk2 = kk + ah_ * 16, hh = kk2 >> 6, d = kk2 & 63;
            size_t off = (((size_t)(b * 8 + hh)) * 4096 + n) * 64 + d;
            uint4 u0 = *(const uint4*)(g_outh + off);
            uint4 u1 = *(const uint4*)(g_outh + off + 8);
            uint4 c0 = *(const uint4*)(g_cvh + off);
            uint4 c1 = *(const uint4*)(g_cvh + off + 8);
            unsigned uo[8] = {u0.x, u0.y, u0.z, u0.w, u1.x, u1.y, u1.z, u1.w};
            unsigned co[8] = {c0.x, c0.y, c0.z, c0.w, c1.x, c1.y, c1.z, c1.w};
#pragma unroll
            for (int i = 0; i < 8; i++) {
                float2 fa = unpackbf(uo[i]), fb = unpackbf(co[i]);
                pr[i] = packbf(fa.x + fb.x, fa.y + fb.y);
            }
        }
    };
    auto storeA = [&](int kk, const unsigned* pr, int bf) {
        unsigned* dst = AsB + bf * 2560 + ar_ * 20 + ah_ * 8;
        if (aMode == 1) {
            float mu = g_mu[rowBase + ar_], rsd = g_rs[rowBase + ar_];
            const float* gp = gammaP + kk + ah_ * 16;
            const float* bp = betaP + kk + ah_ * 16;
#pragma unroll
            for (int i = 0; i < 4; i++) {
                float4 a4 = *(const float4*)&pr[i * 4];
                float4 g4 = ((const float4*)gp)[i];
                float4 b4 = ((const float4*)bp)[i];
                float n0v = (a4.x - mu) * rsd * g4.x + b4.x;
                float n1v = (a4.y - mu) * rsd * g4.y + b4.y;
                float n2v = (a4.z - mu) * rsd * g4.z + b4.z;
                float n3v = (a4.w - mu) * rsd * g4.w + b4.w;
                dst[i * 2]     = packbf(n0v, n1v);
                dst[i * 2 + 1] = packbf(n2v, n3v);
            }
        } else {
            *(uint4*)&dst[0] = *(const uint4*)&pr[0];
            *(uint4*)&dst[4] = *(const uint4*)&pr[4];
        }
    };
    auto fetchB = [&](int kk, float* pr) {
        const float* bp = Bf + (size_t)(kk + 2 * bkp) * ldb + colBase + bn0;
        *(float4*)&pr[0]  = ((const float4*)bp)[0];
        *(float4*)&pr[4]  = ((const float4*)bp)[1];
        *(float4*)&pr[8]  = ((const float4*)(bp + ldb))[0];
        *(float4*)&pr[12] = ((const float4*)(bp + ldb))[1];
    };
    auto storeB = [&](const float* pr, int bf) {
        unsigned* base = BsB + bf * 4608;
#pragma unroll
        for (int j = 0; j < 8; j++) {
            int row = bn0 + j;
            base[row * 36 + bkp + bk_] = packbf(pr[j], pr[8 + j]);
        }
    };

    unsigned prA[16]; float prB[16];
    fetchA(0, prA); fetchB(0, prB);
    storeA(0, prA, 0); storeB(prB, 0);
    __syncthreads();

    int buf = 0;
    for (int k0 = 0; k0 < Kr; k0 += 32) {
        bool nxt = (k0 + 32) < Kr;
        if (nxt) { fetchA(k0 + 32, prA); fetchB(k0 + 32, prB); }
        unsigned* As = AsB + buf * 2560;
        unsigned* Bs = BsB + buf * 4608;
#pragma unroll
        for (int ks = 0; ks < 2; ks++) {
            int kb = ks * 8;
            unsigned arf[4][4], brf[4][2];
#pragma unroll
            for (int mi = 0; mi < 4; mi++) {
                int r = wr * 64 + mi * 16 + r0;
                arf[mi][0] = As[r * 20 + kb + kq];
                arf[mi][1] = As[(r + 8) * 20 + kb + kq];
                arf[mi][2] = As[r * 20 + kb + kq + 4];
                arf[mi][3] = As[(r + 8) * 20 + kb + kq + 4];
            }
#pragma unroll
            for (int ni = 0; ni < 4; ni++) {
                int n = wc * 32 + ni * 8 + r0;
                int sh = (n >> 3) & 15;
                brf[ni][0] = Bs[n * 36 + kb + kq + sh];
                brf[ni][1] = Bs[n * 36 + kb + kq + 4 + sh];
            }
#pragma unroll
            for (int mi = 0; mi < 4; mi++)
#pragma unroll
                for (int ni = 0; ni < 4; ni++) mma16(acc[mi][ni], arf[mi], brf[ni]);
        }
        if (nxt) { storeA(k0 + 32, prA, buf ^ 1); storeB(prB, buf ^ 1); }
        __syncthreads();
        buf ^= 1;
    }

#pragma unroll
    for (int mi = 0; mi < 4; mi++) {
#pragma unroll
        for (int ni = 0; ni < 4; ni++) {
            int rr = rowBase + wr * 64 + mi * 16 + r0;
            int cc = colBase + wc * 32 + ni * 8 + kq * 2;
#pragma unroll
            for (int hf = 0; hf < 2; hf++) {
                int r = rr + hf * 8;
                float v0 = acc[mi][ni][hf * 2];
                float v1 = acc[mi][ni][hf * 2 + 1];
                if (outMode == 1) {
                    int which = cc >> 9, inner = cc & 511;
                    int hh = inner >> 6, d = inner & 63;
                    int b = r >> 12, n = r & 4095;
                    size_t dst = (((size_t)(b * 8 + hh)) * 4096 + n) * 64 + d;
                    if (which == 0)      *(unsigned*)(g_q + dst) = packbf(v0 * QSCALE, v1 * QSCALE);
                    else if (which == 1) *(unsigned*)(g_k + dst) = packbf(v0, v1);
                    else                 *(unsigned*)(g_v + dst) = packbf(v0, v1);
                } else {
                    v0 += bias[cc]; v1 += bias[cc + 1];
                    float2 rx = *(const float2*)(resid + (size_t)r * ldc + cc);
                    v0 += rx.x; v1 += rx.y;
                    *(float2*)(Cf + (size_t)r * ldc + cc) = make_float2(v0, v1);
                }
            }
        }
    }
}

// ---------------- NS GEMM core (K-tile 64, wrapped swizzle) ----------------
template <int MODE>
__device__ __forceinline__ void ns_core(
    const __nv_bfloat16* A, const __nv_bfloat16* B, __nv_bfloat16* C,
    float cM, float cA, const __nv_bfloat16* AE, const __nv_bfloat16* AE2) {
    extern __shared__ unsigned sm[];
    unsigned* AsB = sm;
    unsigned* BsB = sm + 9216;

    int tid = threadIdx.x, lane = tid & 31, w = tid >> 5;
    int wr = w >> 2, wc = w & 3;
    int rowBase = blockIdx.y * 128, colBase = blockIdx.x * 128;
    int r0 = lane >> 2, kq = lane & 3;
    int ar_ = tid >> 1, ah_ = tid & 1;
    int bkp = tid >> 4, bk_ = tid & 15;
    int bn0 = bk_ * 8;

    float acc[4][4][4];
#pragma unroll
    for (int mi = 0; mi < 4; mi++)
#pragma unroll
        for (int ni = 0; ni < 4; ni++)
#pragma unroll
            for (int q = 0; q < 4; q++) acc[mi][ni][q] = 0.f;

    auto fetchA = [&](int kk, uint4* pr) {
        const __nv_bfloat16* ap = A + (size_t)(rowBase + ar_) * 256 + kk + ah_ * 32;
#pragma unroll
        for (int i = 0; i < 4; i++) pr[i] = ((const uint4*)ap)[i];
    };
    auto storeA = [&](const uint4* pr, int bf) {
        unsigned* dst = AsB + bf * 4608 + ar_ * 36 + ah_ * 16;
#pragma unroll
        for (int i = 0; i < 4; i++) *(uint4*)&dst[i * 4] = pr[i];
    };
    auto fetchB = [&](int kk, uint4* pr) {
        const __nv_bfloat16* bp = B + (size_t)(kk + 2 * bkp) * 256 + colBase + bn0;
        pr[0] = *(const uint4*)bp;
        pr[1] = *(const uint4*)(bp + 256);
        const __nv_bfloat16* bp2 = bp + 32 * 256;
        pr[2] = *(const uint4*)bp2;
        pr[3] = *(const uint4*)(bp2 + 256);
    };
    auto storeB = [&](const uint4* pr, int bf) {
        unsigned* base = BsB + bf * 4608;
#pragma unroll
        for (int half = 0; half < 2; half++) {
            int p = bkp + 16 * half;
            int col = (p + bk_) & 31;
            unsigned e[4] = {pr[half*2].x, pr[half*2].y, pr[half*2].z, pr[half*2].w};
            unsigned o[4] = {pr[half*2+1].x, pr[half*2+1].y, pr[half*2+1].z, pr[half*2+1].w};
#pragma unroll
            for (int q2 = 0; q2 < 4; q2++) {
                int n = bn0 + 2 * q2;
                base[n * 36 + col]       = __byte_perm(e[q2], o[q2], 0x5410);
                base[(n + 1) * 36 + col] = __byte_perm(e[q2], o[q2], 0x7632);
            }
        }
    };

    uint4 pA[4], pB[4];
    fetchA(0, pA); fetchB(0, pB);
    storeA(pA, 0); storeB(pB, 0);
    __syncthreads();

    int buf = 0;
    for (int k0 = 0; k0 < 256; k0 += 64) {
        bool nxt = k0 < 192;
        if (nxt) { fetchA(k0 + 64, pA); fetchB(k0 + 64, pB); }
        unsigned* As = AsB + buf * 4608;
        unsigned* Bs = BsB + buf * 4608;
#pragma unroll
        for (int ks = 0; ks < 4; ks++) {
            int kb = ks * 8;
            unsigned arf[4][4], brf[4][2];
#pragma unroll
            for (int mi = 0; mi < 4; mi++) {
                int r = wr * 64 + mi * 16 + r0;
                arf[mi][0] = As[r * 36 + kb + kq];
                arf[mi][1] = As[(r + 8) * 36 + kb + kq];
                arf[mi][2] = As[r * 36 + kb + kq + 4];
                arf[mi][3] = As[(r + 8) * 36 + kb + kq + 4];
            }
#pragma unroll
            for (int ni = 0; ni < 4; ni++) {
                int n = wc * 32 + ni * 8 + r0;
                int sh = n >> 3;
                brf[ni][0] = Bs[n * 36 + ((kb + kq + sh) & 31)];
                brf[ni][1] = Bs[n * 36 + ((kb + kq + 4 + sh) & 31)];
            }
#pragma unroll
            for (int mi = 0; mi < 4; mi++)
#pragma unroll
                for (int ni = 0; ni < 4; ni++) mma16(acc[mi][ni], arf[mi], brf[ni]);
        }
        if (nxt) { storeA(pA, buf ^ 1); storeB(pB, buf ^ 1); }
        __syncthreads();
        buf ^= 1;
    }

#pragma unroll
    for (int mi = 0; mi < 4; mi++) {
#pragma unroll
        for (int ni = 0; ni < 4; ni++) {
            int rr = rowBase + wr * 64 + mi * 16 + r0;
            int cc = colBase + wc * 32 + ni * 8 + kq * 2;
#pragma unroll
            for (int hf = 0; hf < 2; hf++) {
                int r = rr + hf * 8;
                float v0, v1;
                if (MODE == 0) {
                    v0 = cM * acc[mi][ni][hf * 2];
                    v1 = cM * acc[mi][ni][hf * 2 + 1];
                    if (AE) {
                        float2 f = unpackbf(*(const unsigned*)(AE + (size_t)r * 256 + cc));
                        v0 += cA * f.x; v1 += cA * f.y;
                    }
                } else if (MODE == 1) {
                    float2 fy  = unpackbf(*(const unsigned*)(AE + (size_t)r * 256 + cc));
                    float2 fy2 = unpackbf(*(const unsigned*)(AE2 + (size_t)r * 256 + cc));
                    v0 = acc[mi][ni][hf * 2]     + 15.f * fy.x - 7.f * fy2.x;
                    v1 = acc[mi][ni][hf * 2 + 1] + 15.f * fy.y - 7.f * fy2.y;
                } else {
                    float2 f = unpackbf(*(const unsigned*)(AE + (size_t)r * 256 + cc));
                    v0 = -0.25f * acc[mi][ni][hf * 2]     + 3.25f * f.x;
                    v1 = -0.25f * acc[mi][ni][hf * 2 + 1] + 3.25f * f.y;
                }
                *(unsigned*)(C + (size_t)r * 256 + cc) = packbf(v0, v1);
            }
        }
    }
}

__global__ __launch_bounds__(256) void ngemm3(
    const __nv_bfloat16* __restrict__ A, const __nv_bfloat16* __restrict__ B,
    __nv_bfloat16* __restrict__ C, float cM, float cA,
    const __nv_bfloat16* __restrict__ AE) {
    size_t off = (size_t)blockIdx.z << 16;
    ns_core<0>(A + off, B + off, C + off, cM, cA, AE ? AE + off : nullptr, nullptr);
}

__global__ __launch_bounds__(256) void ngemmR(
    const __nv_bfloat16* __restrict__ Y, const __nv_bfloat16* __restrict__ Y2,
    __nv_bfloat16* __restrict__ R) {
    size_t off = (size_t)blockIdx.z << 16;
    ns_core<1>(Y + off, Y2 + off, R + off, 1.f, 0.f, Y + off, Y2 + off);
}

// batched z/y update: bz<32 -> z', bz>=32 -> y'
__global__ __launch_bounds__(256) void ngemmZ(
    const __nv_bfloat16* __restrict__ Zc, __nv_bfloat16* __restrict__ Zo,
    const __nv_bfloat16* __restrict__ Yc, __nv_bfloat16* __restrict__ Yo,
    const __nv_bfloat16* __restrict__ R) {
    int mat = blockIdx.z & 31, sel = blockIdx.z >> 5;
    size_t off = (size_t)mat << 16;
    const __nv_bfloat16* A = (sel ? Yc : Zc) + off;
    __nv_bfloat16*       C = (sel ? Yo : Zo) + off;
    ns_core<2>(A, R + off, C, 0.f, 0.f, A, nullptr);
}

// ---------------- flash attn3 @ v, split-K x4 (register P-fragments) ----------------
__global__ __launch_bounds__(128) void k_flashs() {
    int rt = blockIdx.x, bh = blockIdx.y, sk = blockIdx.z;
    extern __shared__ unsigned sm[];
    unsigned* Qs  = sm;
    unsigned* Ks0 = sm + 2304;
    unsigned* Vt0 = sm + 6912;
    const __nv_bfloat16* qlp = g_ql + (size_t)bh * 16384 + (size_t)rt * 64 * 64;
    const __nv_bfloat16* kp  = g_k + ((size_t)bh << 18);
    const __nv_bfloat16* vp  = g_v + ((size_t)bh << 18);
    int tid = threadIdx.x, lane = tid & 31, w = tid >> 5;
    int r0 = lane >> 2, kq = lane & 3;
    int wrow = w * 16;
    int kr_ = tid >> 1, kh_ = tid & 1;

    auto fetchK = [&](int n0, uint4* pk) {
        const __nv_bfloat16* ap = kp + (size_t)(n0 + kr_) * 64 + kh_ * 32;
#pragma unroll
        for (int i = 0; i < 4; i++) pk[i] = ((const uint4*)ap)[i];
    };
    auto storeK = [&](const uint4* pk, int bf) {
        unsigned* dst = Ks0 + bf * 2304 + kr_ * 36 + kh_ * 16;
#pragma unroll
        for (int i = 0; i < 4; i++) *(uint4*)&dst[i * 4] = pk[i];
    };
    auto fetchV = [&](int n0, uint4* pv) {
#pragma unroll
        for (int it = 0; it < 2; it++) {
            int i = tid + it * 128;
            int sp = i >> 3, dg = i & 7;
            const __nv_bfloat16* ap = vp + (size_t)(n0 + 2 * sp) * 64 + dg * 8;
            pv[it * 2]     = *(const uint4*)ap;
            pv[it * 2 + 1] = *(const uint4*)(ap + 64);
        }
    };
    auto storeV = [&](const uint4* pv, int bf) {
        unsigned* Vt = Vt0 + bf * 2304;
#pragma unroll
        for (int it = 0; it < 2; it++) {
            int i = tid + it * 128;
            int sp = i >> 3, dg = i & 7;
            unsigned av[4] = {pv[it*2].x, pv[it*2].y, pv[it*2].z, pv[it*2].w};
            unsigned bv[4] = {pv[it*2+1].x, pv[it*2+1].y, pv[it*2+1].z, pv[it*2+1].w};
#pragma unroll
            for (int q2 = 0; q2 < 4; q2++) {
                int d0 = dg * 8 + q2 * 2;
                Vt[d0 * 36 + sp]       = __byte_perm(av[q2], bv[q2], 0x5410);
                Vt[(d0 + 1) * 36 + sp] = __byte_perm(av[q2], bv[q2], 0x7632);
            }
        }
    };

    {
        const __nv_bfloat16* ap = qlp + kr_ * 64 + kh_ * 32;
        unsigned* dst = &Qs[kr_ * 36 + kh_ * 16];
#pragma unroll
        for (int i = 0; i < 4; i++) *(uint4*)&dst[i * 4] = ((const uint4*)ap)[i];
    }
    int nBeg = sk * 1024, nEnd = nBeg + 1024;
    uint4 pk[4], pv[4];
    fetchK(nBeg, pk); fetchV(nBeg, pv);
    storeK(pk, 0); storeV(pv, 0);
    __syncthreads();

    float O[8][4];
#pragma unroll
    for (int j = 0; j < 8; j++)
#pragma unroll
        for (int q = 0; q < 4; q++) O[j][q] = 0.f;
    float m0 = -1e30f, m1 = -1e30f, l0 = 0.f, l1 = 0.f;

    int buf = 0;
    for (int n0 = nBeg; n0 < nEnd; n0 += 64) {
        bool nxt = (n0 + 64) < nEnd;
        if (nxt) { fetchK(n0 + 64, pk); fetchV(n0 + 64, pv); }
        unsigned* Ks = Ks0 + buf * 2304;
        unsigned* Vt = Vt0 + buf * 2304;

        float sc[8][4];
#pragma unroll
        for (int j = 0; j < 8; j++)
#pragma unroll
            for (int q = 0; q < 4; q++) sc[j][q] = 0.f;
#pragma unroll
        for (int ks = 0; ks < 4; ks++) {
            int kb = ks * 8;
            unsigned a[4];
            a[0] = Qs[(wrow + r0) * 36 + kb + kq];
            a[1] = Qs[(wrow + r0 + 8) * 36 + kb + kq];
            a[2] = Qs[(wrow + r0) * 36 + kb + kq + 4];
            a[3] = Qs[(wrow + r0 + 8) * 36 + kb + kq + 4];
#pragma unroll
            for (int j = 0; j < 8; j++) {
                unsigned b[2] = { Ks[(j * 8 + r0) * 36 + kb + kq],
                                  Ks[(j * 8 + r0) * 36 + kb + kq + 4] };
                mma16(sc[j], a, b);
            }
        }
        float tm0 = -1e30f, tm1 = -1e30f;
#pragma unroll
        for (int j = 0; j < 8; j++) {
            tm0 = fmaxf(tm0, fmaxf(sc[j][0], sc[j][1]));
            tm1 = fmaxf(tm1, fmaxf(sc[j][2], sc[j][3]));
        }
        tm0 = fmaxf(tm0, __shfl_xor_sync(0xffffffffu, tm0, 1));
        tm0 = fmaxf(tm0, __shfl_xor_sync(0xffffffffu, tm0, 2));
        tm1 = fmaxf(tm1, __shfl_xor_sync(0xffffffffu, tm1, 1));
        tm1 = fmaxf(tm1, __shfl_xor_sync(0xffffffffu, tm1, 2));
        float mn0 = fmaxf(m0, tm0), mn1 = fmaxf(m1, tm1);
        float al0 = __expf(m0 - mn0), al1 = __expf(m1 - mn1);
        float ts0 = 0.f, ts1 = 0.f;
#pragma unroll
        for (int j = 0; j < 8; j++) {
            sc[j][0] = __expf(sc[j][0] - mn0); sc[j][1] = __expf(sc[j][1] - mn0);
            sc[j][2] = __expf(sc[j][2] - mn1); sc[j][3] = __expf(sc[j][3] - mn1);
            ts0 += sc[j][0] + sc[j][1];
            ts1 += sc[j][2] + sc[j][3];
        }
        ts0 += __shfl_xor_sync(0xffffffffu, ts0, 1); ts0 += __shfl_xor_sync(0xffffffffu, ts0, 2);
        ts1 += __shfl_xor_sync(0xffffffffu, ts1, 1); ts1 += __shfl_xor_sync(0xffffffffu, ts1, 2);
        l0 = l0 * al0 + ts0; l1 = l1 * al1 + ts1;
        m0 = mn0; m1 = mn1;
#pragma unroll
        for (int j = 0; j < 8; j++) {
            O[j][0] *= al0; O[j][1] *= al0; O[j][2] *= al1; O[j][3] *= al1;
        }
#pragma unroll
        for (int ks = 0; ks < 4; ks++) {
            unsigned a[4];
            a[0] = packbf(sc[2*ks][0],   sc[2*ks][1]);
            a[1] = packbf(sc[2*ks][2],   sc[2*ks][3]);
            a[2] = packbf(sc[2*ks+1][0], sc[2*ks+1][1]);
            a[3] = packbf(sc[2*ks+1][2], sc[2*ks+1][3]);
            int kb = ks * 8;
#pragma unroll
            for (int j = 0; j < 8; j++) {
                unsigned b[2] = { Vt[(j * 8 + r0) * 36 + kb + kq],
                                  Vt[(j * 8 + r0) * 36 + kb + kq + 4] };
                mma16(O[j], a, b);
            }
        }
        if (nxt) { storeK(pk, buf ^ 1); storeV(pv, buf ^ 1); }
        __syncthreads();
        buf ^= 1;
    }

    float* op = g_fO + ((((size_t)bh * 4 + rt) * 4 + sk) << 12);
#pragma unroll
    for (int j = 0; j < 8; j++) {
        int c = j * 8 + kq * 2;
        op[(wrow + r0) * 64 + c]         = O[j][0];
        op[(wrow + r0) * 64 + c + 1]     = O[j][1];
        op[(wrow + r0 + 8) * 64 + c]     = O[j][2];
        op[(wrow + r0 + 8) * 64 + c + 1] = O[j][3];
    }
    if (kq == 0) {
        int base = (((bh * 4 + rt) * 4) + sk) * 64;
        g_fm[base + wrow + r0]     = m0; g_fl[base + wrow + r0]     = l0;
        g_fm[base + wrow + r0 + 8] = m1; g_fl[base + wrow + r0 + 8] = l1;
    }
}

__global__ void k_fmerge() {
    int bhrt = blockIdx.x, t = threadIdx.x;
    int r = t >> 2, cg = (t & 3) * 16;
    float mv[4], lv[4];
    float M = -1e30f;
#pragma unroll
    for (int sk = 0; sk < 4; sk++) {
        mv[sk] = g_fm[(bhrt * 4 + sk) * 64 + r];
        lv[sk] = g_fl[(bhrt * 4 + sk) * 64 + r];
        M = fmaxf(M, mv[sk]);
    }
    float co[4], L = 0.f;
#pragma unroll
    for (int sk = 0; sk < 4; sk++) { co[sk] = __expf(mv[sk] - M); L += lv[sk] * co[sk]; }
    float inv = 1.f / L;
    int bh = bhrt >> 2, rt = bhrt & 3;
    __nv_bfloat16* op = g_a3v + (size_t)bh * 16384 + rt * 4096 + r * 64 + cg;
#pragma unroll
    for (int cp = 0; cp < 8; cp++) {
        float o0 = 0.f, o1 = 0.f;
#pragma unroll
        for (int sk = 0; sk < 4; sk++) {
            const float* P = g_fO + (((size_t)(bhrt * 4 + sk)) << 12) + r * 64 + cg + cp * 2;
            o0 += co[sk] * P[0];
            o1 += co[sk] * P[1];
        }
        *(unsigned*)(op + cp * 2) = packbf(o0 * inv, o1 * inv);
    }
}

// ---------------- fused attn1, chunked online-softmax, register P ----------------
__global__ __launch_bounds__(256, 2) void k_attn1() {
    int bx = blockIdx.x, bh = blockIdx.y;
    extern __shared__ unsigned sm[];
    unsigned* Qs = sm;
    unsigned* SH = sm + 4608;
    const __nv_bfloat16* qp  = g_q + ((size_t)bh << 18) + (size_t)bx * 128 * 64;
    const __nv_bfloat16* klp = g_kl + (size_t)bh * 16384;
    const __nv_bfloat16* wp  = g_wm + (size_t)bh * 16384;
    int tid = threadIdx.x, lane = tid & 31, w = tid >> 5;
    int r0 = lane >> 2, kq = lane & 3;
    int wrow = w * 16;

    {
        int r = tid >> 1, h = tid & 1;
        const __nv_bfloat16* ap = qp + r * 64 + h * 32;
        unsigned* dst = &Qs[r * 36 + h * 16];
#pragma unroll
        for (int i = 0; i < 4; i++) *(uint4*)&dst[i * 4] = ((const uint4*)ap)[i];
    }

    float O[8][4];
#pragma unroll
    for (int j = 0; j < 8; j++)
#pragma unroll
        for (int q = 0; q < 4; q++) O[j][q] = 0.f;
    float m0 = -1e30f, m1 = -1e30f, l0 = 0.f, l1 = 0.f;

    for (int ch = 0; ch < 2; ch++) {
        __syncthreads();
        {
            int r = tid >> 1, h = tid & 1;
            const __nv_bfloat16* ap = klp + (size_t)(ch * 128 + r) * 64 + h * 32;
            unsigned* dst = &SH[r * 36 + h * 16];
#pragma unroll
            for (int i = 0; i < 4; i++) *(uint4*)&dst[i * 4] = ((const uint4*)ap)[i];
        }
        __syncthreads();

        float sc[16][4];
#pragma unroll
        for (int j = 0; j < 16; j++)
#pragma unroll
            for (int q = 0; q < 4; q++) sc[j][q] = 0.f;
#pragma unroll
        for (int ks = 0; ks < 4; ks++) {
            int kb = ks * 8;
            unsigned a[4];
            a[0] = Qs[(wrow + r0) * 36 + kb + kq];
            a[1] = Qs[(wrow + r0 + 8) * 36 + kb + kq];
            a[2] = Qs[(wrow + r0) * 36 + kb + kq + 4];
            a[3] = Qs[(wrow + r0 + 8) * 36 + kb + kq + 4];
#pragma unroll
            for (int j = 0; j < 16; j++) {
                unsigned b[2] = { SH[(j * 8 + r0) * 36 + kb + kq],
                                  SH[(j * 8 + r0) * 36 + kb + kq + 4] };
                mma16(sc[j], a, b);
            }
        }
        float tm0 = -1e30f, tm1 = -1e30f;
#pragma unroll
        for (int j = 0; j < 16; j++) {
            tm0 = fmaxf(tm0, fmaxf(sc[j][0], sc[j][1]));
            tm1 = fmaxf(tm1, fmaxf(sc[j][2], sc[j][3]));
        }
        tm0 = fmaxf(tm0, __shfl_xor_sync(0xffffffffu, tm0, 1));
        tm0 = fmaxf(tm0, __shfl_xor_sync(0xffffffffu, tm0, 2));
        tm1 = fmaxf(tm1, __shfl_xor_sync(0xffffffffu, tm1, 1));
        tm1 = fmaxf(tm1, __shfl_xor_sync(0xffffffffu, tm1, 2));
        float mn0 = fmaxf(m0, tm0), mn1 = fmaxf(m1, tm1);
        float al0 = __expf(m0 - mn0), al1 = __expf(m1 - mn1);
        float ts0 = 0.f, ts1 = 0.f;
#pragma unroll
        for (int j = 0; j < 16; j++) {
            sc[j][0] = __expf(sc[j][0] - mn0); sc[j][1] = __expf(sc[j][1] - mn0);
            sc[j][2] = __expf(sc[j][2] - mn1); sc[j][3] = __expf(sc[j][3] - mn1);
            ts0 += sc[j][0] + sc[j][1];
            ts1 += sc[j][2] + sc[j][3];
        }
        ts0 += __shfl_xor_sync(0xffffffffu, ts0, 1); ts0 += __shfl_xor_sync(0xffffffffu, ts0, 2);
        ts1 += __shfl_xor_sync(0xffffffffu, ts1, 1); ts1 += __shfl_xor_sync(0xffffffffu, ts1, 2);
        l0 = l0 * al0 + ts0; l1 = l1 * al1 + ts1;
        m0 = mn0; m1 = mn1;
#pragma unroll
        for (int j = 0; j < 8; j++) {
            O[j][0] *= al0; O[j][1] *= al0; O[j][2] *= al1; O[j][3] *= al1;
        }

        __syncthreads();
        {
#pragma unroll
            for (int it = 0; it < 2; it++) {
                int i = tid + it * 256;
                int sp = i >> 3, dg = i & 7;
                const __nv_bfloat16* ap = wp + (size_t)(ch * 128 + 2 * sp) * 64 + dg * 8;
                uint4 ua = *(const uint4*)ap;
                uint4 ub = *(const uint4*)(ap + 64);
                unsigned av[4] = {ua.x, ua.y, ua.z, ua.w};
                unsigned bv[4] = {ub.x, ub.y, ub.z, ub.w};
#pragma unroll
                for (int q2 = 0; q2 < 4; q2++) {
                    int d0 = dg * 8 + q2 * 2;
                    SH[d0 * 68 + sp]       = __byte_perm(av[q2], bv[q2], 0x5410);
                    SH[(d0 + 1) * 68 + sp] = __byte_perm(av[q2], bv[q2], 0x7632);
                }
            }
        }
        __syncthreads();

#pragma unroll
        for (int ks = 0; ks < 8; ks++) {
            unsigned a[4];
            a[0] = packbf(sc[2*ks][0],   sc[2*ks][1]);
            a[1] = packbf(sc[2*ks][2],   sc[2*ks][3]);
            a[2] = packbf(sc[2*ks+1][0], sc[2*ks+1][1]);
            a[3] = packbf(sc[2*ks+1][2], sc[2*ks+1][3]);
            int kb = ks * 8;
#pragma unroll
            for (int j = 0; j < 8; j++) {
                unsigned b[2] = { SH[(j * 8 + r0) * 68 + kb + kq],
                                  SH[(j * 8 + r0) * 68 + kb + kq + 4] };
                mma16(O[j], a, b);
            }
        }
    }

    float il0 = 1.f / l0, il1 = 1.f / l1;
    __nv_bfloat16* op = g_outh + ((size_t)bh << 18) + (size_t)bx * 128 * 64;
#pragma unroll
    for (int j = 0; j < 8; j++) {
        *(unsigned*)(op + (wrow + r0) * 64 + j * 8 + kq * 2)     = packbf(O[j][0] * il0, O[j][1] * il0);
        *(unsigned*)(op + (wrow + r0 + 8) * 64 + j * 8 + kq * 2) = packbf(O[j][2] * il1, O[j][3] * il1);
    }
}

// ---------------- host orchestration ----------------
extern "C" void kernel_launch(void* const* d_in, const int* in_sizes, int n_in,
                              void* d_out, int out_size) {
    const float* x      = (const float*)d_in[0];
    const float* gamma  = (const float*)d_in[1];
    const float* beta   = (const float*)d_in[2];
    const float* w_qkv  = (const float*)d_in[3];
    const float* w_out  = (const float*)d_in[4];
    const float* b_out  = (const float*)d_in[5];
    const float* conv_w = (const float*)d_in[6];
    float* out = (float*)d_out;

    void* tp;
    cudaGetSymbolAddress(&tp, g_a2h);  __nv_bfloat16* p_a2h = (__nv_bfloat16*)tp;
    cudaGetSymbolAddress(&tp, g_z);    __nv_bfloat16* p_z   = (__nv_bfloat16*)tp;
    cudaGetSymbolAddress(&tp, g_zn);   __nv_bfloat16* p_zn  = (__nv_bfloat16*)tp;
    cudaGetSymbolAddress(&tp, g_az);   __nv_bfloat16* p_y   = (__nv_bfloat16*)tp;
    cudaGetSymbolAddress(&tp, g_w1);   __nv_bfloat16* p_y2  = (__nv_bfloat16*)tp;
    cudaGetSymbolAddress(&tp, g_w2);   __nv_bfloat16* p_r   = (__nv_bfloat16*)tp;
    cudaGetSymbolAddress(&tp, g_a3v);  __nv_bfloat16* p_a3v = (__nv_bfloat16*)tp;
    cudaGetSymbolAddress(&tp, g_wm);   __nv_bfloat16* p_wm  = (__nv_bfloat16*)tp;

    static cudaStream_t s2 = nullptr;
    static cudaEvent_t evF = nullptr, evJ = nullptr;
    if (!s2) {
        cudaStreamCreateWithFlags(&s2, cudaStreamNonBlocking);
        cudaEventCreateWithFlags(&evF, cudaEventDisableTiming);
        cudaEventCreateWithFlags(&evJ, cudaEventDisableTiming);
    }

    cudaFuncSetAttribute(k_flashs, cudaFuncAttributeMaxDynamicSharedMemorySize, 46080);
    cudaFuncSetAttribute(k_attn1,  cudaFuncAttributeMaxDynamicSharedMemorySize, 36864);
    cudaFuncSetAttribute(k_score2, cudaFuncAttributeMaxDynamicSharedMemorySize, 46080);
    cudaFuncSetAttribute(bgemm,    cudaFuncAttributeMaxDynamicSharedMemorySize, 57344);
    cudaFuncSetAttribute(ngemm3,   cudaFuncAttributeMaxDynamicSharedMemorySize, 73728);
    cudaFuncSetAttribute(ngemmR,   cudaFuncAttributeMaxDynamicSharedMemorySize, 73728);
    cudaFuncSetAttribute(ngemmZ,   cudaFuncAttributeMaxDynamicSharedMemorySize, 73728);

    k_lnstats<<<Bb * Nn, 256>>>(x);

    // qkv = LN(x) @ w_qkv -> scatter bf16 q/k/v
    bgemm<<<dim3(12, 128, 1), 256, 57344>>>(x, w_qkv, nullptr, 512, 512, 1536, 1536,
        1, 1, nullptr, nullptr, gamma, beta);

    k_land<<<(2 * BHc * Mm * 32) / 256, 256>>>();

    // ---- fork: flash chain + conv on s2 ----
    cudaEventRecord(evF, 0);
    cudaStreamWaitEvent(s2, evF, 0);
    k_flashs<<<dim3(4, 32, 4), 128, 46080, s2>>>();
    k_fmerge<<<128, 256, 0, s2>>>();
    k_conv2<<<dim3(32, 32), 256, 0, s2>>>(conv_w);
    cudaEventRecord(evJ, s2);

    // main chain: scores(+colsum) -> sums -> z0 -> y0 -> NS
    k_score2<<<dim3(4, 32), 128, 46080>>>();
    k_sums<<<BHc, 256>>>();
    k_z0<<<(BHc * Mm * Mm / 2) / 256, 256>>>();

    // y0 = a2 @ z0
    ngemm3<<<dim3(2, 2, 32), 256, 73728>>>(p_a2h, p_z, p_y, 1.f, 0.f, nullptr);

    __nv_bfloat16* zc = p_z;   __nv_bfloat16* zo = p_zn;
    __nv_bfloat16* yc = p_y;   __nv_bfloat16* yo = p_a2h;
    for (int it = 0; it < 6; it++) {
        ngemm3<<<dim3(2, 2, 32), 256, 73728>>>(yc, yc, p_y2, 1.f, 0.f, nullptr);
        ngemmR<<<dim3(2, 2, 32), 256, 73728>>>(yc, p_y2, p_r);
        if (it < 5) {
            ngemmZ<<<dim3(2, 2, 64), 256, 73728>>>(zc, zo, yc, yo, p_r);
            __nv_bfloat16* t;
            t = zc; zc = zo; zo = t;
            t = yc; yc = yo; yo = t;
        } else {
            ngemmZ<<<dim3(2, 2, 32), 256, 73728>>>(zc, zo, yc, yo, p_r);
            __nv_bfloat16* t = zc; zc = zo; zo = t;
        }
    }

    // ---- join ----
    cudaStreamWaitEvent(0, evJ, 0);

    // wm = Z @ a3v
    tgemm<<<dim3(1, 2, 32), 256>>>(zc, p_a3v, p_wm, 256, 256, 64, 64,
        (long)Mm * Mm, (long)Mm * Dd, (long)Mm * Dd);

    // fused attn1 -> outh
    k_attn1<<<dim3(32, 32), 256, 36864>>>();

    // final: out = (merge(outh)+cvh) @ w_out + b_out + x
    bgemm<<<dim3(4, 128, 1), 256, 57344>>>(nullptr, w_out, out, 512, 512, 512, 512,
        2, 2, b_out, x, nullptr, nullptr);
}

// round 16
// speedup vs baseline: 1.0532x; 1.0367x over previous
#include <cuda_runtime.h>
#include <cuda_bf16.h>
#include <cstddef>

#define Bb 4
#define Nn 4096
#define DIMV 512
#define Hh 8
#define Dd 64
#define Mm 256
#define BHc 32
#define QSCALE 0.125f

// ---------------- scratch ----------------
__device__ __nv_bfloat16 g_q   [BHc*Nn*Dd];
__device__ __nv_bfloat16 g_k   [BHc*Nn*Dd];
__device__ __nv_bfloat16 g_v   [BHc*Nn*Dd];
__device__ __nv_bfloat16 g_ql  [BHc*Mm*Dd];
__device__ __nv_bfloat16 g_kl  [BHc*Mm*Dd];
__device__ __nv_bfloat16 g_a2h [BHc*Mm*Mm];   // A2; reused as y ping buffer
__device__ __nv_bfloat16 g_z   [BHc*Mm*Mm];
__device__ __nv_bfloat16 g_zn  [BHc*Mm*Mm];
__device__ __nv_bfloat16 g_az  [BHc*Mm*Mm];   // y
__device__ __nv_bfloat16 g_w1  [BHc*Mm*Mm];   // y^2
__device__ __nv_bfloat16 g_w2  [BHc*Mm*Mm];   // r
__device__ __nv_bfloat16 g_a3v [BHc*Mm*Dd];
__device__ __nv_bfloat16 g_wm  [BHc*Mm*Dd];
__device__ __nv_bfloat16 g_outh[BHc*Nn*Dd];
__device__ __nv_bfloat16 g_cvh [BHc*Nn*Dd];
__device__ float g_mu[Bb*Nn];
__device__ float g_rs[Bb*Nn];
__device__ float g_ms2;
__device__ float g_fO[BHc*4*4*4096];
__device__ float g_fm[BHc*4*4*64];
__device__ float g_fl[BHc*4*4*64];

__device__ __forceinline__ unsigned packbf(float a, float b) {
    __nv_bfloat162 t = __floats2bfloat162_rn(a, b);
    return *reinterpret_cast<unsigned*>(&t);
}
__device__ __forceinline__ float2 unpackbf(unsigned u) {
    __nv_bfloat162 t = *reinterpret_cast<__nv_bfloat162*>(&u);
    return make_float2(__bfloat162float(t.x), __bfloat162float(t.y));
}
__device__ __forceinline__ void mma16(float* c, const unsigned* a, const unsigned* b) {
    asm volatile("mma.sync.aligned.m16n8k16.row.col.f32.bf16.bf16.f32 "
                 "{%0,%1,%2,%3},{%4,%5,%6,%7},{%8,%9},{%0,%1,%2,%3};"
                 : "+f"(c[0]), "+f"(c[1]), "+f"(c[2]), "+f"(c[3])
                 : "r"(a[0]), "r"(a[1]), "r"(a[2]), "r"(a[3]), "r"(b[0]), "r"(b[1]));
}

// ---------------- small kernels ----------------
// LN stats: warp-per-row, 8 rows/block, grid 2048
__global__ __launch_bounds__(256) void k_lnstats(const float* __restrict__ x) {
    int wid = threadIdx.x >> 5, lane = threadIdx.x & 31;
    int r = blockIdx.x * 8 + wid;
    if (blockIdx.x == 0 && threadIdx.x == 0) g_ms2 = 0.f;
    const float* xp = x + (size_t)r * DIMV + lane * 16;
    float s = 0.f, s2 = 0.f;
#pragma unroll
    for (int i = 0; i < 4; i++) {
        float4 v = ((const float4*)xp)[i];
        s  += v.x + v.y + v.z + v.w;
        s2 += v.x * v.x + v.y * v.y + v.z * v.z + v.w * v.w;
    }
#pragma unroll
    for (int o = 16; o; o >>= 1) {
        s  += __shfl_xor_sync(0xffffffffu, s, o);
        s2 += __shfl_xor_sync(0xffffffffu, s2, o);
    }
    if (lane == 0) {
        float mean = s * (1.f / 512.f);
        float var = s2 * (1.f / 512.f) - mean * mean;
        g_mu[r] = mean;
        g_rs[r] = rsqrtf(var + 1e-5f);
    }
}

__global__ void k_land() {
    int idx = blockIdx.x * 256 + threadIdx.x;
    int sel = idx >= (BHc * Mm * 32);
    int e = idx & (BHc * Mm * 32 - 1);
    int bh = e >> 13, j = (e >> 5) & 255, dp = e & 31;
    const __nv_bfloat16* src = sel ? g_k : g_q;
    const __nv_bfloat16* p = src + ((size_t)bh * 4096 + j * 16) * 64 + dp * 2;
    float s0 = 0.f, s1 = 0.f;
#pragma unroll
    for (int t = 0; t < 16; t++) {
        float2 f = unpackbf(*(const unsigned*)(p + t * 64));
        s0 += f.x; s1 += f.y;
    }
    __nv_bfloat16* dst = sel ? g_kl : g_ql;
    *(unsigned*)(dst + (size_t)bh * 16384 + j * 64 + dp * 2) =
        packbf(s0 * (1.f / 16.f), s1 * (1.f / 16.f));
}

// max column-sum of softmaxed a2 (bf16 source)
__global__ void k_sums() {
    int mat = blockIdx.x, t = threadIdx.x;
    const __nv_bfloat16* A = g_a2h + ((size_t)mat << 16);
    float cs = 0.f;
    for (int i = 0; i < 256; i++) cs += __bfloat162float(A[i * 256 + t]);
    __shared__ float red[256];
    red[t] = cs; __syncthreads();
    for (int s = 128; s; s >>= 1) { if (t < s) red[t] = fmaxf(red[t], red[t + s]); __syncthreads(); }
    if (!t) atomicMax((int*)&g_ms2, __float_as_int(red[0]));
}

// z0 = a2h^T / ms2
__global__ void k_z0() {
    int p = blockIdx.x * 256 + threadIdx.x;
    float inv = 1.f / g_ms2;
    int mat = p >> 15, rem = p & 32767;
    int r = rem >> 7, cp = (rem & 127) * 2;
    const __nv_bfloat16* A = g_a2h + ((size_t)mat << 16);
    float t0 = __bfloat162float(A[(size_t)cp * 256 + r]);
    float t1 = __bfloat162float(A[(size_t)(cp + 1) * 256 + r]);
    *(unsigned*)(g_z + ((size_t)mat << 16) + (size_t)r * 256 + cp) = packbf(t0 * inv, t1 * inv);
}

__global__ void k_conv2(const float* __restrict__ w) {
    int nt = blockIdx.x, bh = blockIdx.y;
    __shared__ float vs[160][64];
    const __nv_bfloat16* vp = g_v + ((size_t)bh << 18);
    int n0 = nt * 128;
    for (int i = threadIdx.x; i < 160 * 8; i += 256) {
        int r = i >> 3, g = i & 7;
        int n = n0 - 16 + r;
        if (n >= 0 && n < 4096) {
            uint4 u = *(const uint4*)(vp + (size_t)n * 64 + g * 8);
            float2 f0 = unpackbf(u.x), f1 = unpackbf(u.y), f2 = unpackbf(u.z), f3 = unpackbf(u.w);
            vs[r][g * 8 + 0] = f0.x; vs[r][g * 8 + 1] = f0.y;
            vs[r][g * 8 + 2] = f1.x; vs[r][g * 8 + 3] = f1.y;
            vs[r][g * 8 + 4] = f2.x; vs[r][g * 8 + 5] = f2.y;
            vs[r][g * 8 + 6] = f3.x; vs[r][g * 8 + 7] = f3.y;
        } else {
#pragma unroll
            for (int q = 0; q < 8; q++) vs[r][g * 8 + q] = 0.f;
        }
    }
    __syncthreads();
    int h = bh & 7;
    float wr[33];
#pragma unroll
    for (int t = 0; t < 33; t++) wr[t] = w[h * 33 + t];
    int dp = threadIdx.x & 31, nl = threadIdx.x >> 5;
    for (int p = 0; p < 16; p++) {
        int n = nl + p * 8;
        float a0 = 0.f, a1 = 0.f;
#pragma unroll
        for (int t = 0; t < 33; t++) {
            a0 += wr[t] * vs[n + t][dp * 2];
            a1 += wr[t] * vs[n + t][dp * 2 + 1];
        }
        *(unsigned*)(g_cvh + ((size_t)bh * 4096 + n0 + n) * 64 + dp * 2) = packbf(a0, a1);
    }
}

// ---------------- fused scores+softmax, 64 rows/block (bf16 out only) ----------------
__global__ __launch_bounds__(128) void k_score2() {
    int bx = blockIdx.x, bh = blockIdx.y;
    extern __shared__ unsigned sm[];
    unsigned* Qs  = sm;
    unsigned* KLs = sm + 2304;
    const __nv_bfloat16* qlp = g_ql + (size_t)bh * 16384 + (size_t)bx * 64 * 64;
    const __nv_bfloat16* klp = g_kl + (size_t)bh * 16384;
    int tid = threadIdx.x, lane = tid & 31, w = tid >> 5;
    int r0 = lane >> 2, kq = lane & 3;
    int wrow = w * 16;

    {
        int r = tid >> 1, h = tid & 1;
        const __nv_bfloat16* ap = qlp + r * 64 + h * 32;
        unsigned* dst = &Qs[r * 36 + h * 16];
#pragma unroll
        for (int i = 0; i < 4; i++) *(uint4*)&dst[i * 4] = ((const uint4*)ap)[i];
    }
#pragma unroll
    for (int rr = 0; rr < 2; rr++) {
        int r = tid + rr * 128;
        const __nv_bfloat16* ap = klp + r * 64;
        unsigned* dst = &KLs[r * 36];
#pragma unroll
        for (int i = 0; i < 8; i++) *(uint4*)&dst[i * 4] = ((const uint4*)ap)[i];
    }
    __syncthreads();

    float sc[32][4];
#pragma unroll
    for (int j = 0; j < 32; j++)
#pragma unroll
        for (int q = 0; q < 4; q++) sc[j][q] = 0.f;
#pragma unroll
    for (int ks = 0; ks < 4; ks++) {
        int kb = ks * 8;
        unsigned a[4];
        a[0] = Qs[(wrow + r0) * 36 + kb + kq];
        a[1] = Qs[(wrow + r0 + 8) * 36 + kb + kq];
        a[2] = Qs[(wrow + r0) * 36 + kb + kq + 4];
        a[3] = Qs[(wrow + r0 + 8) * 36 + kb + kq + 4];
#pragma unroll
        for (int j = 0; j < 32; j++) {
            unsigned b[2] = { KLs[(j * 8 + r0) * 36 + kb + kq],
                              KLs[(j * 8 + r0) * 36 + kb + kq + 4] };
            mma16(sc[j], a, b);
        }
    }
    float m0 = -1e30f, m1 = -1e30f;
#pragma unroll
    for (int j = 0; j < 32; j++) {
        m0 = fmaxf(m0, fmaxf(sc[j][0], sc[j][1]));
        m1 = fmaxf(m1, fmaxf(sc[j][2], sc[j][3]));
    }
    m0 = fmaxf(m0, __shfl_xor_sync(0xffffffffu, m0, 1));
    m0 = fmaxf(m0, __shfl_xor_sync(0xffffffffu, m0, 2));
    m1 = fmaxf(m1, __shfl_xor_sync(0xffffffffu, m1, 1));
    m1 = fmaxf(m1, __shfl_xor_sync(0xffffffffu, m1, 2));
    float l0 = 0.f, l1 = 0.f;
#pragma unroll
    for (int j = 0; j < 32; j++) {
        sc[j][0] = __expf(sc[j][0] - m0); sc[j][1] = __expf(sc[j][1] - m0);
        sc[j][2] = __expf(sc[j][2] - m1); sc[j][3] = __expf(sc[j][3] - m1);
        l0 += sc[j][0] + sc[j][1];
        l1 += sc[j][2] + sc[j][3];
    }
    l0 += __shfl_xor_sync(0xffffffffu, l0, 1); l0 += __shfl_xor_sync(0xffffffffu, l0, 2);
    l1 += __shfl_xor_sync(0xffffffffu, l1, 1); l1 += __shfl_xor_sync(0xffffffffu, l1, 2);
    float il0 = 1.f / l0, il1 = 1.f / l1;

    __nv_bfloat16* ho = g_a2h + ((size_t)bh << 16);
    int rlo = bx * 64 + wrow + r0, rhi = rlo + 8;
#pragma unroll
    for (int j = 0; j < 32; j++) {
        int c = j * 8 + kq * 2;
        *(unsigned*)(ho + (size_t)rlo * 256 + c) = packbf(sc[j][0] * il0, sc[j][1] * il0);
        *(unsigned*)(ho + (size_t)rhi * 256 + c) = packbf(sc[j][2] * il1, sc[j][3] * il1);
    }
}

// ---------------- pipelined bf16 GEMM 128x64 (wm only) ----------------
__global__ __launch_bounds__(256) void tgemm(
    const void* Av, const void* Bv, void* Cv, int Kr,
    int lda, int ldb, int ldc, long sA, long sB, long sC) {
    int bz = blockIdx.z;
    const __nv_bfloat16* Ab = (const __nv_bfloat16*)Av + (size_t)bz * sA;
    const __nv_bfloat16* Bh = (const __nv_bfloat16*)Bv + (size_t)bz * sB;
    __nv_bfloat16*       Cb = (__nv_bfloat16*)Cv + (size_t)bz * sC;

    __shared__ unsigned As[2][128][20];
    __shared__ unsigned Bs[2][64][20];

    int tid = threadIdx.x, lane = tid & 31, w = tid >> 5;
    int wr = w >> 1, wc = w & 1;
    int rowBase = blockIdx.y * 128, colBase = blockIdx.x * 64;
    int r0 = lane >> 2, kq = lane & 3;
    int ar_ = tid >> 1, ah_ = tid & 1;
    int bkp = tid >> 4, bn0 = (tid & 15) * 4;

    float acc[2][4][4];
#pragma unroll
    for (int mi = 0; mi < 2; mi++)
#pragma unroll
        for (int ni = 0; ni < 4; ni++)
#pragma unroll
            for (int q = 0; q < 4; q++) acc[mi][ni][q] = 0.f;

    auto fetchA = [&](int kk, unsigned* pr) {
        const __nv_bfloat16* ap = Ab + (size_t)(rowBase + ar_) * lda + kk + ah_ * 16;
        *(uint4*)&pr[0] = *(const uint4*)ap;
        *(uint4*)&pr[4] = *(const uint4*)(ap + 8);
    };
    auto storeA = [&](const unsigned* pr, int bf) {
        unsigned* dst = &As[bf][ar_][ah_ * 8];
        *(uint4*)&dst[0] = *(const uint4*)&pr[0];
        *(uint4*)&dst[4] = *(const uint4*)&pr[4];
    };
    auto fetchB = [&](int kk, unsigned* pr) {
        const __nv_bfloat16* bp = Bh + (size_t)(kk + 2 * bkp) * ldb + colBase + bn0;
        *(uint2*)&pr[0] = *(const uint2*)bp;
        *(uint2*)&pr[2] = *(const uint2*)(bp + ldb);
    };
    auto storeB = [&](const unsigned* pr, int bf) {
        uint2 r1 = *(const uint2*)&pr[0];
        uint2 r2 = *(const uint2*)&pr[2];
        Bs[bf][bn0 + 0][bkp] = __byte_perm(r1.x, r2.x, 0x5410);
        Bs[bf][bn0 + 1][bkp] = __byte_perm(r1.x, r2.x, 0x7632);
        Bs[bf][bn0 + 2][bkp] = __byte_perm(r1.y, r2.y, 0x5410);
        Bs[bf][bn0 + 3][bkp] = __byte_perm(r1.y, r2.y, 0x7632);
    };

    unsigned prA[8], prB[4];
    fetchA(0, prA); fetchB(0, prB);
    storeA(prA, 0); storeB(prB, 0);
    __syncthreads();

    int buf = 0;
    for (int k0 = 0; k0 < Kr; k0 += 32) {
        bool nxt = (k0 + 32) < Kr;
        if (nxt) { fetchA(k0 + 32, prA); fetchB(k0 + 32, prB); }
#pragma unroll
        for (int ks = 0; ks < 2; ks++) {
            int kb = ks * 8;
            unsigned arf[2][4], brf[4][2];
#pragma unroll
            for (int mi = 0; mi < 2; mi++) {
                int r = wr * 32 + mi * 16 + r0;
                arf[mi][0] = As[buf][r][kb + kq];
                arf[mi][1] = As[buf][r + 8][kb + kq];
                arf[mi][2] = As[buf][r][kb + kq + 4];
                arf[mi][3] = As[buf][r + 8][kb + kq + 4];
            }
#pragma unroll
            for (int ni = 0; ni < 4; ni++) {
                int n = wc * 32 + ni * 8 + r0;
                brf[ni][0] = Bs[buf][n][kb + kq];
                brf[ni][1] = Bs[buf][n][kb + kq + 4];
            }
#pragma unroll
            for (int mi = 0; mi < 2; mi++)
#pragma unroll
                for (int ni = 0; ni < 4; ni++) mma16(acc[mi][ni], arf[mi], brf[ni]);
        }
        if (nxt) { storeA(prA, buf ^ 1); storeB(prB, buf ^ 1); }
        __syncthreads();
        buf ^= 1;
    }

#pragma unroll
    for (int mi = 0; mi < 2; mi++) {
#pragma unroll
        for (int ni = 0; ni < 4; ni++) {
            int rr = rowBase + wr * 32 + mi * 16 + r0;
            int cc = colBase + wc * 32 + ni * 8 + kq * 2;
#pragma unroll
            for (int hf = 0; hf < 2; hf++) {
                int r = rr + hf * 8;
                *(unsigned*)(Cb + (size_t)r * ldc + cc) =
                    packbf(acc[mi][ni][hf * 2], acc[mi][ni][hf * 2 + 1]);
            }
        }
    }
}

// ---------------- big-tile GEMM 128x128 (qkv + final) ----------------
__global__ __launch_bounds__(256) void bgemm(
    const float* __restrict__ Af, const float* __restrict__ Bf, void* Cv,
    int Kr, int lda, int ldb, int ldc, int aMode, int outMode,
    const float* __restrict__ bias, const float* __restrict__ resid,
    const float* __restrict__ gammaP, const float* __restrict__ betaP) {
    extern __shared__ unsigned sm[];
    unsigned* AsB = sm;
    unsigned* BsB = sm + 5120;

    float* Cf = (float*)Cv;

    int tid = threadIdx.x, lane = tid & 31, w = tid >> 5;
    int wr = w >> 2, wc = w & 3;
    int rowBase = blockIdx.y * 128, colBase = blockIdx.x * 128;
    int r0 = lane >> 2, kq = lane & 3;
    int ar_ = tid >> 1, ah_ = tid & 1;
    int bkp = tid >> 4, bk_ = tid & 15;
    int bn0 = bk_ * 8;

    float acc[4][4][4];
#pragma unroll
    for (int mi = 0; mi < 4; mi++)
#pragma unroll
        for (int ni = 0; ni < 4; ni++)
#pragma unroll
            for (int q = 0; q < 4; q++) acc[mi][ni][q] = 0.f;

    auto fetchA = [&](int kk, unsigned* pr) {
        if (aMode == 1) {
            const float* ap = Af + (size_t)(rowBase + ar_) * lda + kk + ah_ * 16;
            *(float4*)&pr[0]  = ((const float4*)ap)[0];
            *(float4*)&pr[4]  = ((const float4*)ap)[1];
            *(float4*)&pr[8]  = ((const float4*)ap)[2];
            *(float4*)&pr[12] = ((const float4*)ap)[3];
        } else {
            int gr = rowBase + ar_;
            int b = gr >> 12, n = gr & 4095;
            int kk2 = kk + ah_ * 16, hh = kk2 >> 6, d = kk2 & 63;
            size_t off = (((size_t)(b * 8 + hh)) * 4096 + n) * 64 + d;
            uint4 u0 = *(const uint4*)(g_outh + off);
            uint4 u1 = *(const uint4*)(g_outh + off + 8);
            uint4 c0 = *(const uint4*)(g_cvh + off);
            uint4 c1 = *(const uint4*)(g_cvh + off + 8);
            unsigned uo[8] = {u0.x, u0.y, u0.z, u0.w, u1.x, u1.y, u1.z, u1.w};
            unsigned co[8] = {c0.x, c0.y, c0.z, c0.w, c1.x, c1.y, c1.z, c1.w};
#pragma unroll
            for (int i = 0; i < 8; i++) {
                float2 fa = unpackbf(uo[i]), fb = unpackbf(co[i]);
                pr[i] = packbf(fa.x + fb.x, fa.y + fb.y);
            }
        }
    };
    auto storeA = [&](int kk, const unsigned* pr, int bf) {
        unsigned* dst = AsB + bf * 2560 + ar_ * 20 + ah_ * 8;
        if (aMode == 1) {
            float mu = g_mu[rowBase + ar_], rsd = g_rs[rowBase + ar_];
            const float* gp = gammaP + kk + ah_ * 16;
            const float* bp = betaP + kk + ah_ * 16;
#pragma unroll
            for (int i = 0; i < 4; i++) {
                float4 a4 = *(const float4*)&pr[i * 4];
                float4 g4 = ((const float4*)gp)[i];
                float4 b4 = ((const float4*)bp)[i];
                float n0v = (a4.x - mu) * rsd * g4.x + b4.x;
                float n1v = (a4.y - mu) * rsd * g4.y + b4.y;
                float n2v = (a4.z - mu) * rsd * g4.z + b4.z;
                float n3v = (a4.w - mu) * rsd * g4.w + b4.w;
                dst[i * 2]     = packbf(n0v, n1v);
                dst[i * 2 + 1] = packbf(n2v, n3v);
            }
        } else {
            *(uint4*)&dst[0] = *(const uint4*)&pr[0];
            *(uint4*)&dst[4] = *(const uint4*)&pr[4];
        }
    };
    auto fetchB = [&](int kk, float* pr) {
        const float* bp = Bf + (size_t)(kk + 2 * bkp) * ldb + colBase + bn0;
        *(float4*)&pr[0]  = ((const float4*)bp)[0];
        *(float4*)&pr[4]  = ((const float4*)bp)[1];
        *(float4*)&pr[8]  = ((const float4*)(bp + ldb))[0];
        *(float4*)&pr[12] = ((const float4*)(bp + ldb))[1];
    };
    auto storeB = [&](const float* pr, int bf) {
        unsigned* base = BsB + bf * 4608;
#pragma unroll
        for (int j = 0; j < 8; j++) {
            int row = bn0 + j;
            base[row * 36 + bkp + bk_] = packbf(pr[j], pr[8 + j]);
        }
    };

    unsigned prA[16]; float prB[16];
    fetchA(0, prA); fetchB(0, prB);
    storeA(0, prA, 0); storeB(prB, 0);
    __syncthreads();

    int buf = 0;
    for (int k0 = 0; k0 < Kr; k0 += 32) {
        bool nxt = (k0 + 32) < Kr;
        if (nxt) { fetchA(k0 + 32, prA); fetchB(k0 + 32, prB); }
        unsigned* As = AsB + buf * 2560;
        unsigned* Bs = BsB + buf * 4608;
#pragma unroll
        for (int ks = 0; ks < 2; ks++) {
            int kb = ks * 8;
            unsigned arf[4][4], brf[4][2];
#pragma unroll
            for (int mi = 0; mi < 4; mi++) {
                int r = wr * 64 + mi * 16 + r0;
                arf[mi][0] = As[r * 20 + kb + kq];
                arf[mi][1] = As[(r + 8) * 20 + kb + kq];
                arf[mi][2] = As[r * 20 + kb + kq + 4];
                arf[mi][3] = As[(r + 8) * 20 + kb + kq + 4];
            }
#pragma unroll
            for (int ni = 0; ni < 4; ni++) {
                int n = wc * 32 + ni * 8 + r0;
                int sh = (n >> 3) & 15;
                brf[ni][0] = Bs[n * 36 + kb + kq + sh];
                brf[ni][1] = Bs[n * 36 + kb + kq + 4 + sh];
            }
#pragma unroll
            for (int mi = 0; mi < 4; mi++)
#pragma unroll
                for (int ni = 0; ni < 4; ni++) mma16(acc[mi][ni], arf[mi], brf[ni]);
        }
        if (nxt) { storeA(k0 + 32, prA, buf ^ 1); storeB(prB, buf ^ 1); }
        __syncthreads();
        buf ^= 1;
    }

#pragma unroll
    for (int mi = 0; mi < 4; mi++) {
#pragma unroll
        for (int ni = 0; ni < 4; ni++) {
            int rr = rowBase + wr * 64 + mi * 16 + r0;
            int cc = colBase + wc * 32 + ni * 8 + kq * 2;
#pragma unroll
            for (int hf = 0; hf < 2; hf++) {
                int r = rr + hf * 8;
                float v0 = acc[mi][ni][hf * 2];
                float v1 = acc[mi][ni][hf * 2 + 1];
                if (outMode == 1) {
                    int which = cc >> 9, inner = cc & 511;
                    int hh = inner >> 6, d = inner & 63;
                    int b = r >> 12, n = r & 4095;
                    size_t dst = (((size_t)(b * 8 + hh)) * 4096 + n) * 64 + d;
                    if (which == 0)      *(unsigned*)(g_q + dst) = packbf(v0 * QSCALE, v1 * QSCALE);
                    else if (which == 1) *(unsigned*)(g_k + dst) = packbf(v0, v1);
                    else                 *(unsigned*)(g_v + dst) = packbf(v0, v1);
                } else {
                    v0 += bias[cc]; v1 += bias[cc + 1];
                    float2 rx = *(const float2*)(resid + (size_t)r * ldc + cc);
                    v0 += rx.x; v1 += rx.y;
                    *(float2*)(Cf + (size_t)r * ldc + cc) = make_float2(v0, v1);
                }
            }
        }
    }
}

// ---------------- NS GEMM core (K-tile 64, wrapped swizzle) ----------------
template <int MODE>
__device__ __forceinline__ void ns_core(
    const __nv_bfloat16* A, const __nv_bfloat16* B, __nv_bfloat16* C,
    float cM, float cA, const __nv_bfloat16* AE, const __nv_bfloat16* AE2) {
    extern __shared__ unsigned sm[];
    unsigned* AsB = sm;
    unsigned* BsB = sm + 9216;

    int tid = threadIdx.x, lane = tid & 31, w = tid >> 5;
    int wr = w >> 2, wc = w & 3;
    int rowBase = blockIdx.y * 128, colBase = blockIdx.x * 128;
    int r0 = lane >> 2, kq = lane & 3;
    int ar_ = tid >> 1, ah_ = tid & 1;
    int bkp = tid >> 4, bk_ = tid & 15;
    int bn0 = bk_ * 8;

    float acc[4][4][4];
#pragma unroll
    for (int mi = 0; mi < 4; mi++)
#pragma unroll
        for (int ni = 0; ni < 4; ni++)
#pragma unroll
            for (int q = 0; q < 4; q++) acc[mi][ni][q] = 0.f;

    auto fetchA = [&](int kk, uint4* pr) {
        const __nv_bfloat16* ap = A + (size_t)(rowBase + ar_) * 256 + kk + ah_ * 32;
#pragma unroll
        for (int i = 0; i < 4; i++) pr[i] = ((const uint4*)ap)[i];
    };
    auto storeA = [&](const uint4* pr, int bf) {
        unsigned* dst = AsB + bf * 4608 + ar_ * 36 + ah_ * 16;
#pragma unroll
        for (int i = 0; i < 4; i++) *(uint4*)&dst[i * 4] = pr[i];
    };
    auto fetchB = [&](int kk, uint4* pr) {
        const __nv_bfloat16* bp = B + (size_t)(kk + 2 * bkp) * 256 + colBase + bn0;
        pr[0] = *(const uint4*)bp;
        pr[1] = *(const uint4*)(bp + 256);
        const __nv_bfloat16* bp2 = bp + 32 * 256;
        pr[2] = *(const uint4*)bp2;
        pr[3] = *(const uint4*)(bp2 + 256);
    };
    auto storeB = [&](const uint4* pr, int bf) {
        unsigned* base = BsB + bf * 4608;
#pragma unroll
        for (int half = 0; half < 2; half++) {
            int p = bkp + 16 * half;
            int col = (p + bk_) & 31;
            unsigned e[4] = {pr[half*2].x, pr[half*2].y, pr[half*2].z, pr[half*2].w};
            unsigned o[4] = {pr[half*2+1].x, pr[half*2+1].y, pr[half*2+1].z, pr[half*2+1].w};
#pragma unroll
            for (int q2 = 0; q2 < 4; q2++) {
                int n = bn0 + 2 * q2;
                base[n * 36 + col]       = __byte_perm(e[q2], o[q2], 0x5410);
                base[(n + 1) * 36 + col] = __byte_perm(e[q2], o[q2], 0x7632);
            }
        }
    };

    uint4 pA[4], pB[4];
    fetchA(0, pA); fetchB(0, pB);
    storeA(pA, 0); storeB(pB, 0);
    __syncthreads();

    int buf = 0;
    for (int k0 = 0; k0 < 256; k0 += 64) {
        bool nxt = k0 < 192;
        if (nxt) { fetchA(k0 + 64, pA); fetchB(k0 + 64, pB); }
        unsigned* As = AsB + buf * 4608;
        unsigned* Bs = BsB + buf * 4608;
#pragma unroll
        for (int ks = 0; ks < 4; ks++) {
            int kb = ks * 8;
            unsigned arf[4][4], brf[4][2];
#pragma unroll
            for (int mi = 0; mi < 4; mi++) {
                int r = wr * 64 + mi * 16 + r0;
                arf[mi][0] = As[r * 36 + kb + kq];
                arf[mi][1] = As[(r + 8) * 36 + kb + kq];
                arf[mi][2] = As[r * 36 + kb + kq + 4];
                arf[mi][3] = As[(r + 8) * 36 + kb + kq + 4];
            }
#pragma unroll
            for (int ni = 0; ni < 4; ni++) {
                int n = wc * 32 + ni * 8 + r0;
                int sh = n >> 3;
                brf[ni][0] = Bs[n * 36 + ((kb + kq + sh) & 31)];
                brf[ni][1] = Bs[n * 36 + ((kb + kq + 4 + sh) & 31)];
            }
#pragma unroll
            for (int mi = 0; mi < 4; mi++)
#pragma unroll
                for (int ni = 0; ni < 4; ni++) mma16(acc[mi][ni], arf[mi], brf[ni]);
        }
        if (nxt) { storeA(pA, buf ^ 1); storeB(pB, buf ^ 1); }
        __syncthreads();
        buf ^= 1;
    }

#pragma unroll
    for (int mi = 0; mi < 4; mi++) {
#pragma unroll
        for (int ni = 0; ni < 4; ni++) {
            int rr = rowBase + wr * 64 + mi * 16 + r0;
            int cc = colBase + wc * 32 + ni * 8 + kq * 2;
#pragma unroll
            for (int hf = 0; hf < 2; hf++) {
                int r = rr + hf * 8;
                float v0, v1;
                if (MODE == 0) {
                    v0 = cM * acc[mi][ni][hf * 2];
                    v1 = cM * acc[mi][ni][hf * 2 + 1];
                    if (AE) {
                        float2 f = unpackbf(*(const unsigned*)(AE + (size_t)r * 256 + cc));
                        v0 += cA * f.x; v1 += cA * f.y;
                    }
                } else if (MODE == 1) {
                    float2 fy  = unpackbf(*(const unsigned*)(AE + (size_t)r * 256 + cc));
                    float2 fy2 = unpackbf(*(const unsigned*)(AE2 + (size_t)r * 256 + cc));
                    v0 = acc[mi][ni][hf * 2]     + 15.f * fy.x - 7.f * fy2.x;
                    v1 = acc[mi][ni][hf * 2 + 1] + 15.f * fy.y - 7.f * fy2.y;
                } else {
                    float2 f = unpackbf(*(const unsigned*)(AE + (size_t)r * 256 + cc));
                    v0 = -0.25f * acc[mi][ni][hf * 2]     + 3.25f * f.x;
                    v1 = -0.25f * acc[mi][ni][hf * 2 + 1] + 3.25f * f.y;
                }
                *(unsigned*)(C + (size_t)r * 256 + cc) = packbf(v0, v1);
            }
        }
    }
}

__global__ __launch_bounds__(256) void ngemm3(
    const __nv_bfloat16* __restrict__ A, const __nv_bfloat16* __restrict__ B,
    __nv_bfloat16* __restrict__ C, float cM, float cA,
    const __nv_bfloat16* __restrict__ AE) {
    size_t off = (size_t)blockIdx.z << 16;
    ns_core<0>(A + off, B + off, C + off, cM, cA, AE ? AE + off : nullptr, nullptr);
}

__global__ __launch_bounds__(256) void ngemmR(
    const __nv_bfloat16* __restrict__ Y, const __nv_bfloat16* __restrict__ Y2,
    __nv_bfloat16* __restrict__ R) {
    size_t off = (size_t)blockIdx.z << 16;
    ns_core<1>(Y + off, Y2 + off, R + off, 1.f, 0.f, Y + off, Y2 + off);
}

__global__ __launch_bounds__(256) void ngemmZ(
    const __nv_bfloat16* __restrict__ Zc, __nv_bfloat16* __restrict__ Zo,
    const __nv_bfloat16* __restrict__ Yc, __nv_bfloat16* __restrict__ Yo,
    const __nv_bfloat16* __restrict__ R) {
    int mat = blockIdx.z & 31, sel = blockIdx.z >> 5;
    size_t off = (size_t)mat << 16;
    const __nv_bfloat16* A = (sel ? Yc : Zc) + off;
    __nv_bfloat16*       C = (sel ? Yo : Zo) + off;
    ns_core<2>(A, R + off, C, 0.f, 0.f, A, nullptr);
}

// ---------------- flash attn3 @ v, split-K x4 (register P-fragments) ----------------
__global__ __launch_bounds__(128) void k_flashs() {
    int rt = blockIdx.x, bh = blockIdx.y, sk = blockIdx.z;
    extern __shared__ unsigned sm[];
    unsigned* Qs  = sm;
    unsigned* Ks0 = sm + 2304;
    unsigned* Vt0 = sm + 6912;
    const __nv_bfloat16* qlp = g_ql + (size_t)bh * 16384 + (size_t)rt * 64 * 64;
    const __nv_bfloat16* kp  = g_k + ((size_t)bh << 18);
    const __nv_bfloat16* vp  = g_v + ((size_t)bh << 18);
    int tid = threadIdx.x, lane = tid & 31, w = tid >> 5;
    int r0 = lane >> 2, kq = lane & 3;
    int wrow = w * 16;
    int kr_ = tid >> 1, kh_ = tid & 1;

    auto fetchK = [&](int n0, uint4* pk) {
        const __nv_bfloat16* ap = kp + (size_t)(n0 + kr_) * 64 + kh_ * 32;
#pragma unroll
        for (int i = 0; i < 4; i++) pk[i] = ((const uint4*)ap)[i];
    };
    auto storeK = [&](const uint4* pk, int bf) {
        unsigned* dst = Ks0 + bf * 2304 + kr_ * 36 + kh_ * 16;
#pragma unroll
        for (int i = 0; i < 4; i++) *(uint4*)&dst[i * 4] = pk[i];
    };
    auto fetchV = [&](int n0, uint4* pv) {
#pragma unroll
        for (int it = 0; it < 2; it++) {
            int i = tid + it * 128;
            int sp = i >> 3, dg = i & 7;
            const __nv_bfloat16* ap = vp + (size_t)(n0 + 2 * sp) * 64 + dg * 8;
            pv[it * 2]     = *(const uint4*)ap;
            pv[it * 2 + 1] = *(const uint4*)(ap + 64);
        }
    };
    auto storeV = [&](const uint4* pv, int bf) {
        unsigned* Vt = Vt0 + bf * 2304;
#pragma unroll
        for (int it = 0; it < 2; it++) {
            int i = tid + it * 128;
            int sp = i >> 3, dg = i & 7;
            unsigned av[4] = {pv[it*2].x, pv[it*2].y, pv[it*2].z, pv[it*2].w};
            unsigned bv[4] = {pv[it*2+1].x, pv[it*2+1].y, pv[it*2+1].z, pv[it*2+1].w};
#pragma unroll
            for (int q2 = 0; q2 < 4; q2++) {
                int d0 = dg * 8 + q2 * 2;
                Vt[d0 * 36 + sp]       = __byte_perm(av[q2], bv[q2], 0x5410);
                Vt[(d0 + 1) * 36 + sp] = __byte_perm(av[q2], bv[q2], 0x7632);
            }
        }
    };

    {
        const __nv_bfloat16* ap = qlp + kr_ * 64 + kh_ * 32;
        unsigned* dst = &Qs[kr_ * 36 + kh_ * 16];
#pragma unroll
        for (int i = 0; i < 4; i++) *(uint4*)&dst[i * 4] = ((const uint4*)ap)[i];
    }
    int nBeg = sk * 1024, nEnd = nBeg + 1024;
    uint4 pk[4], pv[4];
    fetchK(nBeg, pk); fetchV(nBeg, pv);
    storeK(pk, 0); storeV(pv, 0);
    __syncthreads();

    float O[8][4];
#pragma unroll
    for (int j = 0; j < 8; j++)
#pragma unroll
        for (int q = 0; q < 4; q++) O[j][q] = 0.f;
    float m0 = -1e30f, m1 = -1e30f, l0 = 0.f, l1 = 0.f;

    int buf = 0;
    for (int n0 = nBeg; n0 < nEnd; n0 += 64) {
        bool nxt = (n0 + 64) < nEnd;
        if (nxt) { fetchK(n0 + 64, pk); fetchV(n0 + 64, pv); }
        unsigned* Ks = Ks0 + buf * 2304;
        unsigned* Vt = Vt0 + buf * 2304;

        float sc[8][4];
#pragma unroll
        for (int j = 0; j < 8; j++)
#pragma unroll
            for (int q = 0; q < 4; q++) sc[j][q] = 0.f;
#pragma unroll
        for (int ks = 0; ks < 4; ks++) {
            int kb = ks * 8;
            unsigned a[4];
            a[0] = Qs[(wrow + r0) * 36 + kb + kq];
            a[1] = Qs[(wrow + r0 + 8) * 36 + kb + kq];
            a[2] = Qs[(wrow + r0) * 36 + kb + kq + 4];
            a[3] = Qs[(wrow + r0 + 8) * 36 + kb + kq + 4];
#pragma unroll
            for (int j = 0; j < 8; j++) {
                unsigned b[2] = { Ks[(j * 8 + r0) * 36 + kb + kq],
                                  Ks[(j * 8 + r0) * 36 + kb + kq + 4] };
                mma16(sc[j], a, b);
            }
        }
        float tm0 = -1e30f, tm1 = -1e30f;
#pragma unroll
        for (int j = 0; j < 8; j++) {
            tm0 = fmaxf(tm0, fmaxf(sc[j][0], sc[j][1]));
            tm1 = fmaxf(tm1, fmaxf(sc[j][2], sc[j][3]));
        }
        tm0 = fmaxf(tm0, __shfl_xor_sync(0xffffffffu, tm0, 1));
        tm0 = fmaxf(tm0, __shfl_xor_sync(0xffffffffu, tm0, 2));
        tm1 = fmaxf(tm1, __shfl_xor_sync(0xffffffffu, tm1, 1));
        tm1 = fmaxf(tm1, __shfl_xor_sync(0xffffffffu, tm1, 2));
        float mn0 = fmaxf(m0, tm0), mn1 = fmaxf(m1, tm1);
        float al0 = __expf(m0 - mn0), al1 = __expf(m1 - mn1);
        float ts0 = 0.f, ts1 = 0.f;
#pragma unroll
        for (int j = 0; j < 8; j++) {
            sc[j][0] = __expf(sc[j][0] - mn0); sc[j][1] = __expf(sc[j][1] - mn0);
            sc[j][2] = __expf(sc[j][2] - mn1); sc[j][3] = __expf(sc[j][3] - mn1);
            ts0 += sc[j][0] + sc[j][1];
            ts1 += sc[j][2] + sc[j][3];
        }
        ts0 += __shfl_xor_sync(0xffffffffu, ts0, 1); ts0 += __shfl_xor_sync(0xffffffffu, ts0, 2);
        ts1 += __shfl_xor_sync(0xffffffffu, ts1, 1); ts1 += __shfl_xor_sync(0xffffffffu, ts1, 2);
        l0 = l0 * al0 + ts0; l1 = l1 * al1 + ts1;
        m0 = mn0; m1 = mn1;
#pragma unroll
        for (int j = 0; j < 8; j++) {
            O[j][0] *= al0; O[j][1] *= al0; O[j][2] *= al1; O[j][3] *= al1;
        }
#pragma unroll
        for (int ks = 0; ks < 4; ks++) {
            unsigned a[4];
            a[0] = packbf(sc[2*ks][0],   sc[2*ks][1]);
            a[1] = packbf(sc[2*ks][2],   sc[2*ks][3]);
            a[2] = packbf(sc[2*ks+1][0], sc[2*ks+1][1]);
            a[3] = packbf(sc[2*ks+1][2], sc[2*ks+1][3]);
            int kb = ks * 8;
#pragma unroll
            for (int j = 0; j < 8; j++) {
                unsigned b[2] = { Vt[(j * 8 + r0) * 36 + kb + kq],
                                  Vt[(j * 8 + r0) * 36 + kb + kq + 4] };
                mma16(O[j], a, b);
            }
        }
        if (nxt) { storeK(pk, buf ^ 1); storeV(pv, buf ^ 1); }
        __syncthreads();
        buf ^= 1;
    }

    float* op = g_fO + ((((size_t)bh * 4 + rt) * 4 + sk) << 12);
#pragma unroll
    for (int j = 0; j < 8; j++) {
        int c = j * 8 + kq * 2;
        op[(wrow + r0) * 64 + c]         = O[j][0];
        op[(wrow + r0) * 64 + c + 1]     = O[j][1];
        op[(wrow + r0 + 8) * 64 + c]     = O[j][2];
        op[(wrow + r0 + 8) * 64 + c + 1] = O[j][3];
    }
    if (kq == 0) {
        int base = (((bh * 4 + rt) * 4) + sk) * 64;
        g_fm[base + wrow + r0]     = m0; g_fl[base + wrow + r0]     = l0;
        g_fm[base + wrow + r0 + 8] = m1; g_fl[base + wrow + r0 + 8] = l1;
    }
}

__global__ void k_fmerge() {
    int bhrt = blockIdx.x, t = threadIdx.x;
    int r = t >> 2, cg = (t & 3) * 16;
    float mv[4], lv[4];
    float M = -1e30f;
#pragma unroll
    for (int sk = 0; sk < 4; sk++) {
        mv[sk] = g_fm[(bhrt * 4 + sk) * 64 + r];
        lv[sk] = g_fl[(bhrt * 4 + sk) * 64 + r];
        M = fmaxf(M, mv[sk]);
    }
    float co[4], L = 0.f;
#pragma unroll
    for (int sk = 0; sk < 4; sk++) { co[sk] = __expf(mv[sk] - M); L += lv[sk] * co[sk]; }
    float inv = 1.f / L;
    int bh = bhrt >> 2, rt = bhrt & 3;
    __nv_bfloat16* op = g_a3v + (size_t)bh * 16384 + rt * 4096 + r * 64 + cg;
#pragma unroll
    for (int cp = 0; cp < 8; cp++) {
        float o0 = 0.f, o1 = 0.f;
#pragma unroll
        for (int sk = 0; sk < 4; sk++) {
            const float* P = g_fO + (((size_t)(bhrt * 4 + sk)) << 12) + r * 64 + cg + cp * 2;
            o0 += co[sk] * P[0];
            o1 += co[sk] * P[1];
        }
        *(unsigned*)(op + cp * 2) = packbf(o0 * inv, o1 * inv);
    }
}

// ---------------- fused attn1, chunked online-softmax, register P ----------------
__global__ __launch_bounds__(256, 2) void k_attn1() {
    int bx = blockIdx.x, bh = blockIdx.y;
    extern __shared__ unsigned sm[];
    unsigned* Qs = sm;
    unsigned* SH = sm + 4608;
    const __nv_bfloat16* qp  = g_q + ((size_t)bh << 18) + (size_t)bx * 128 * 64;
    const __nv_bfloat16* klp = g_kl + (size_t)bh * 16384;
    const __nv_bfloat16* wp  = g_wm + (size_t)bh * 16384;
    int tid = threadIdx.x, lane = tid & 31, w = tid >> 5;
    int r0 = lane >> 2, kq = lane & 3;
    int wrow = w * 16;

    {
        int r = tid >> 1, h = tid & 1;
        const __nv_bfloat16* ap = qp + r * 64 + h * 32;
        unsigned* dst = &Qs[r * 36 + h * 16];
#pragma unroll
        for (int i = 0; i < 4; i++) *(uint4*)&dst[i * 4] = ((const uint4*)ap)[i];
    }

    float O[8][4];
#pragma unroll
    for (int j = 0; j < 8; j++)
#pragma unroll
        for (int q = 0; q < 4; q++) O[j][q] = 0.f;
    float m0 = -1e30f, m1 = -1e30f, l0 = 0.f, l1 = 0.f;

    for (int ch = 0; ch < 2; ch++) {
        __syncthreads();
        {
            int r = tid >> 1, h = tid & 1;
            const __nv_bfloat16* ap = klp + (size_t)(ch * 128 + r) * 64 + h * 32;
            unsigned* dst = &SH[r * 36 + h * 16];
#pragma unroll
            for (int i = 0; i < 4; i++) *(uint4*)&dst[i * 4] = ((const uint4*)ap)[i];
        }
        __syncthreads();

        float sc[16][4];
#pragma unroll
        for (int j = 0; j < 16; j++)
#pragma unroll
            for (int q = 0; q < 4; q++) sc[j][q] = 0.f;
#pragma unroll
        for (int ks = 0; ks < 4; ks++) {
            int kb = ks * 8;
            unsigned a[4];
            a[0] = Qs[(wrow + r0) * 36 + kb + kq];
            a[1] = Qs[(wrow + r0 + 8) * 36 + kb + kq];
            a[2] = Qs[(wrow + r0) * 36 + kb + kq + 4];
            a[3] = Qs[(wrow + r0 + 8) * 36 + kb + kq + 4];
#pragma unroll
            for (int j = 0; j < 16; j++) {
                unsigned b[2] = { SH[(j * 8 + r0) * 36 + kb + kq],
                                  SH[(j * 8 + r0) * 36 + kb + kq + 4] };
                mma16(sc[j], a, b);
            }
        }
        float tm0 = -1e30f, tm1 = -1e30f;
#pragma unroll
        for (int j = 0; j < 16; j++) {
            tm0 = fmaxf(tm0, fmaxf(sc[j][0], sc[j][1]));
            tm1 = fmaxf(tm1, fmaxf(sc[j][2], sc[j][3]));
        }
        tm0 = fmaxf(tm0, __shfl_xor_sync(0xffffffffu, tm0, 1));
        tm0 = fmaxf(tm0, __shfl_xor_sync(0xffffffffu, tm0, 2));
        tm1 = fmaxf(tm1, __shfl_xor_sync(0xffffffffu, tm1, 1));
        tm1 = fmaxf(tm1, __shfl_xor_sync(0xffffffffu, tm1, 2));
        float mn0 = fmaxf(m0, tm0), mn1 = fmaxf(m1, tm1);
        float al0 = __expf(m0 - mn0), al1 = __expf(m1 - mn1);
        float ts0 = 0.f, ts1 = 0.f;
#pragma unroll
        for (int j = 0; j < 16; j++) {
            sc[j][0] = __expf(sc[j][0] - mn0); sc[j][1] = __expf(sc[j][1] - mn0);
            sc[j][2] = __expf(sc[j][2] - mn1); sc[j][3] = __expf(sc[j][3] - mn1);
            ts0 += sc[j][0] + sc[j][1];
            ts1 += sc[j][2] + sc[j][3];
        }
        ts0 += __shfl_xor_sync(0xffffffffu, ts0, 1); ts0 += __shfl_xor_sync(0xffffffffu, ts0, 2);
        ts1 += __shfl_xor_sync(0xffffffffu, ts1, 1); ts1 += __shfl_xor_sync(0xffffffffu, ts1, 2);
        l0 = l0 * al0 + ts0; l1 = l1 * al1 + ts1;
        m0 = mn0; m1 = mn1;
#pragma unroll
        for (int j = 0; j < 8; j++) {
            O[j][0] *= al0; O[j][1] *= al0; O[j][2] *= al1; O[j][3] *= al1;
        }

        __syncthreads();
        {
#pragma unroll
            for (int it = 0; it < 2; it++) {
                int i = tid + it * 256;
                int sp = i >> 3, dg = i & 7;
                const __nv_bfloat16* ap = wp + (size_t)(ch * 128 + 2 * sp) * 64 + dg * 8;
                uint4 ua = *(const uint4*)ap;
                uint4 ub = *(const uint4*)(ap + 64);
                unsigned av[4] = {ua.x, ua.y, ua.z, ua.w};
                unsigned bv[4] = {ub.x, ub.y, ub.z, ub.w};
#pragma unroll
                for (int q2 = 0; q2 < 4; q2++) {
                    int d0 = dg * 8 + q2 * 2;
                    SH[d0 * 68 + sp]       = __byte_perm(av[q2], bv[q2], 0x5410);
                    SH[(d0 + 1) * 68 + sp] = __byte_perm(av[q2], bv[q2], 0x7632);
                }
            }
        }
        __syncthreads();

#pragma unroll
        for (int ks = 0; ks < 8; ks++) {
            unsigned a[4];
            a[0] = packbf(sc[2*ks][0],   sc[2*ks][1]);
            a[1] = packbf(sc[2*ks][2],   sc[2*ks][3]);
            a[2] = packbf(sc[2*ks+1][0], sc[2*ks+1][1]);
            a[3] = packbf(sc[2*ks+1][2], sc[2*ks+1][3]);
            int kb = ks * 8;
#pragma unroll
            for (int j = 0; j < 8; j++) {
                unsigned b[2] = { SH[(j * 8 + r0) * 68 + kb + kq],
                                  SH[(j * 8 + r0) * 68 + kb + kq + 4] };
                mma16(O[j], a, b);
            }
        }
    }

    float il0 = 1.f / l0, il1 = 1.f / l1;
    __nv_bfloat16* op = g_outh + ((size_t)bh << 18) + (size_t)bx * 128 * 64;
#pragma unroll
    for (int j = 0; j < 8; j++) {
        *(unsigned*)(op + (wrow + r0) * 64 + j * 8 + kq * 2)     = packbf(O[j][0] * il0, O[j][1] * il0);
        *(unsigned*)(op + (wrow + r0 + 8) * 64 + j * 8 + kq * 2) = packbf(O[j][2] * il1, O[j][3] * il1);
    }
}

// ---------------- host orchestration ----------------
extern "C" void kernel_launch(void* const* d_in, const int* in_sizes, int n_in,
                              void* d_out, int out_size) {
    const float* x      = (const float*)d_in[0];
    const float* gamma  = (const float*)d_in[1];
    const float* beta   = (const float*)d_in[2];
    const float* w_qkv  = (const float*)d_in[3];
    const float* w_out  = (const float*)d_in[4];
    const float* b_out  = (const float*)d_in[5];
    const float* conv_w = (const float*)d_in[6];
    float* out = (float*)d_out;

    void* tp;
    cudaGetSymbolAddress(&tp, g_a2h);  __nv_bfloat16* p_a2h = (__nv_bfloat16*)tp;
    cudaGetSymbolAddress(&tp, g_z);    __nv_bfloat16* p_z   = (__nv_bfloat16*)tp;
    cudaGetSymbolAddress(&tp, g_zn);   __nv_bfloat16* p_zn  = (__nv_bfloat16*)tp;
    cudaGetSymbolAddress(&tp, g_az);   __nv_bfloat16* p_y   = (__nv_bfloat16*)tp;
    cudaGetSymbolAddress(&tp, g_w1);   __nv_bfloat16* p_y2  = (__nv_bfloat16*)tp;
    cudaGetSymbolAddress(&tp, g_w2);   __nv_bfloat16* p_r   = (__nv_bfloat16*)tp;
    cudaGetSymbolAddress(&tp, g_a3v);  __nv_bfloat16* p_a3v = (__nv_bfloat16*)tp;
    cudaGetSymbolAddress(&tp, g_wm);   __nv_bfloat16* p_wm  = (__nv_bfloat16*)tp;

    static cudaStream_t s2 = nullptr;
    static cudaEvent_t evF = nullptr, evJ = nullptr;
    if (!s2) {
        cudaStreamCreateWithFlags(&s2, cudaStreamNonBlocking);
        cudaEventCreateWithFlags(&evF, cudaEventDisableTiming);
        cudaEventCreateWithFlags(&evJ, cudaEventDisableTiming);
    }

    cudaFuncSetAttribute(k_flashs, cudaFuncAttributeMaxDynamicSharedMemorySize, 46080);
    cudaFuncSetAttribute(k_attn1,  cudaFuncAttributeMaxDynamicSharedMemorySize, 36864);
    cudaFuncSetAttribute(k_score2, cudaFuncAttributeMaxDynamicSharedMemorySize, 46080);
    cudaFuncSetAttribute(bgemm,    cudaFuncAttributeMaxDynamicSharedMemorySize, 57344);
    cudaFuncSetAttribute(ngemm3,   cudaFuncAttributeMaxDynamicSharedMemorySize, 73728);
    cudaFuncSetAttribute(ngemmR,   cudaFuncAttributeMaxDynamicSharedMemorySize, 73728);
    cudaFuncSetAttribute(ngemmZ,   cudaFuncAttributeMaxDynamicSharedMemorySize, 73728);

    k_lnstats<<<Bb * Nn / 8, 256>>>(x);

    // qkv = LN(x) @ w_qkv -> scatter bf16 q/k/v
    bgemm<<<dim3(12, 128, 1), 256, 57344>>>(x, w_qkv, nullptr, 512, 512, 1536, 1536,
        1, 1, nullptr, nullptr, gamma, beta);

    k_land<<<(2 * BHc * Mm * 32) / 256, 256>>>();

    // ---- fork: flash chain + conv on s2 ----
    cudaEventRecord(evF, 0);
    cudaStreamWaitEvent(s2, evF, 0);
    k_flashs<<<dim3(4, 32, 4), 128, 46080, s2>>>();
    k_fmerge<<<128, 256, 0, s2>>>();
    k_conv2<<<dim3(32, 32), 256, 0, s2>>>(conv_w);
    cudaEventRecord(evJ, s2);

    // main chain: scores -> sums -> z0 -> y0 -> NS
    k_score2<<<dim3(4, 32), 128, 46080>>>();
    k_sums<<<BHc, 256>>>();
    k_z0<<<(BHc * Mm * Mm / 2) / 256, 256>>>();

    // y0 = a2 @ z0
    ngemm3<<<dim3(2, 2, 32), 256, 73728>>>(p_a2h, p_z, p_y, 1.f, 0.f, nullptr);

    __nv_bfloat16* zc = p_z;   __nv_bfloat16* zo = p_zn;
    __nv_bfloat16* yc = p_y;   __nv_bfloat16* yo = p_a2h;
    for (int it = 0; it < 6; it++) {
        ngemm3<<<dim3(2, 2, 32), 256, 73728>>>(yc, yc, p_y2, 1.f, 0.f, nullptr);
        ngemmR<<<dim3(2, 2, 32), 256, 73728>>>(yc, p_y2, p_r);
        if (it < 5) {
            ngemmZ<<<dim3(2, 2, 64), 256, 73728>>>(zc, zo, yc, yo, p_r);
            __nv_bfloat16* t;
            t = zc; zc = zo; zo = t;
            t = yc; yc = yo; yo = t;
        } else {
            ngemmZ<<<dim3(2, 2, 32), 256, 73728>>>(zc, zo, yc, yo, p_r);
            __nv_bfloat16* t = zc; zc = zo; zo = t;
        }
    }

    // ---- join ----
    cudaStreamWaitEvent(0, evJ, 0);

    // wm = Z @ a3v
    tgemm<<<dim3(1, 2, 32), 256>>>(zc, p_a3v, p_wm, 256, 256, 64, 64,
        (long)Mm * Mm, (long)Mm * Dd, (long)Mm * Dd);

    // fused attn1 -> outh
    k_attn1<<<dim3(32, 32), 256, 36864>>>();

    // final: out = (merge(outh)+cvh) @ w_out + b_out + x
    bgemm<<<dim3(4, 128, 1), 256, 57344>>>(nullptr, w_out, out, 512, 512, 512, 512,
        2, 2, b_out, x, nullptr, nullptr);
}